// round 13
// baseline (speedup 1.0000x reference)
#include <cuda_runtime.h>
#include <cuda_fp16.h>
#include <cstdint>

#define S_LEN 2048
#define HID 2048
#define NH 32
#define NKV 8
#define HD 64
#define QKV_OUT 3072   // (32 + 2*8) * 64

// ---------------- scratch (static device globals; no allocation) ----------------
__device__ __align__(16) __half g_xh[S_LEN * HID],  g_xl[S_LEN * HID];
__device__ __align__(16) __half g_wqh[QKV_OUT * HID], g_wql[QKV_OUT * HID];
__device__ __align__(16) __half g_woh[HID * HID],   g_wol[HID * HID];
__device__ __align__(16) __half g_qhh[NH * S_LEN * HD],  g_qhl[NH * S_LEN * HD];
__device__ __align__(16) __half g_khh[NKV * S_LEN * HD], g_khl[NKV * S_LEN * HD];
__device__ __align__(16) __half g_vhh[NKV * S_LEN * HD], g_vhl[NKV * S_LEN * HD];
__device__ __align__(16) __half g_ahh[S_LEN * HID], g_ahl[S_LEN * HID];

// ============================ helpers ============================
__device__ __forceinline__ uint32_t smem_u32(const void* p) {
    uint32_t a;
    asm("{ .reg .u64 t; cvta.to.shared.u64 t, %1; cvt.u32.u64 %0, t; }"
        : "=r"(a) : "l"(p));
    return a;
}
__device__ __forceinline__ void cp16(uint32_t s, const void* g) {
    asm volatile("cp.async.cg.shared.global [%0], [%1], 16;" :: "r"(s), "l"(g));
}
#define CP_COMMIT() asm volatile("cp.async.commit_group;" ::: "memory")

__device__ __forceinline__ void ldmx4(uint32_t* r, uint32_t addr) {
    asm volatile("ldmatrix.sync.aligned.m8n8.x4.shared.b16 {%0,%1,%2,%3}, [%4];"
                 : "=r"(r[0]), "=r"(r[1]), "=r"(r[2]), "=r"(r[3]) : "r"(addr));
}
__device__ __forceinline__ void ldmx4t(uint32_t* r, uint32_t addr) {
    asm volatile("ldmatrix.sync.aligned.m8n8.x4.trans.shared.b16 {%0,%1,%2,%3}, [%4];"
                 : "=r"(r[0]), "=r"(r[1]), "=r"(r[2]), "=r"(r[3]) : "r"(addr));
}
__device__ __forceinline__ void mma_h(float* d, const uint32_t* a,
                                      const uint32_t* b) {
    asm volatile(
        "mma.sync.aligned.m16n8k16.row.col.f32.f16.f16.f32 "
        "{%0,%1,%2,%3}, {%4,%5,%6,%7}, {%8,%9}, {%0,%1,%2,%3};"
        : "+f"(d[0]), "+f"(d[1]), "+f"(d[2]), "+f"(d[3])
        : "r"(a[0]), "r"(a[1]), "r"(a[2]), "r"(a[3]), "r"(b[0]), "r"(b[1]));
}
__device__ __forceinline__ float ex2(float x) {
    float y;
    asm("ex2.approx.ftz.f32 %0, %1;" : "=f"(y) : "f"(x));
    return y;
}
__device__ __forceinline__ void split2(float a, float b, uint32_t& hp, uint32_t& lp) {
    __half ha = __float2half_rn(a), hb = __float2half_rn(b);
    hp = (uint32_t)__half_as_ushort(ha) | ((uint32_t)__half_as_ushort(hb) << 16);
    __half la = __float2half_rn(a - __half2float(ha));
    __half lb = __float2half_rn(b - __half2float(hb));
    lp = (uint32_t)__half_as_ushort(la) | ((uint32_t)__half_as_ushort(lb) << 16);
}

// ============================================================================
// fp16 split-precision GEMM (3-pass), fp32 accum.
// CTA 128(M)x256(N), 512 threads, 4x4 warp grid, warp tile 32x64, BK=32,
// 2-stage cp.async. Square warp grid halves smem crossbar traffic per MAC
// (AI 8 -> 16 MACs/LDSM-byte) so the HMMA pipe, not smem, is the binder.
// MODE 0: fp32 C out.  MODE 1: fused RoPE + hi/lo split + [h][s][d] scatter.
// ============================================================================
#define BK 32
#define ROWB 80                          // 64B data + 16B pad
#define OFF_AH 0
#define OFF_AL (128 * ROWB)              // 10240
#define OFF_BH (2 * 128 * ROWB)          // 20480
#define OFF_BL (2 * 128 * ROWB + 256 * ROWB)  // 40960
#define STAGE_B (OFF_BL + 256 * ROWB)    // 61440
#define GEMM_SMEM (2 * STAGE_B)          // 122880

template <int MODE>
__global__ __launch_bounds__(512, 1) void gemm_hs(
    const __half* __restrict__ Ah, const __half* __restrict__ Al,
    const __half* __restrict__ Bh, const __half* __restrict__ Bl,
    float* __restrict__ C, const float* __restrict__ cosb,
    const float* __restrict__ sinb, int N, int K) {
    extern __shared__ __align__(128) char dsm[];
    const uint32_t base = smem_u32(dsm);

    const int tid = threadIdx.x;
    const int wid = tid >> 5;
    const int lane = tid & 31;
    const int wn = wid & 3;              // 0..3 : warp col (64 cols each)
    const int wm = wid >> 2;             // 0..3 : warp row (32 rows each)
    const int bm = blockIdx.y * 128;
    const int bn = blockIdx.x * 256;
    const int nchunk = K / BK;

    float acc[2][8][4];
#pragma unroll
    for (int i = 0; i < 2; i++)
#pragma unroll
        for (int j = 0; j < 8; j++)
#pragma unroll
            for (int k = 0; k < 4; k++) acc[i][j][k] = 0.f;

    auto load_chunk = [&](int chunk, int stage) {
        const int k0 = chunk * BK;
        const uint32_t sb = base + stage * STAGE_B;
        {   // A hi/lo: 512 cp16 each, one per thread
            int r = tid >> 2, cc = tid & 3;
            uint32_t so = (uint32_t)(r * ROWB + cc * 16);
            size_t g = (size_t)(bm + r) * K + k0 + cc * 8;
            cp16(sb + OFF_AH + so, Ah + g);
            cp16(sb + OFF_AL + so, Al + g);
        }
#pragma unroll
        for (int i = 0; i < 2; i++) {    // B hi/lo: 1024 cp16 each
            int c = tid + i * 512;
            int r = c >> 2, cc = c & 3;
            uint32_t so = (uint32_t)(r * ROWB + cc * 16);
            size_t g = (size_t)(bn + r) * K + k0 + cc * 8;
            cp16(sb + OFF_BH + so, Bh + g);
            cp16(sb + OFF_BL + so, Bl + g);
        }
        CP_COMMIT();
    };

    const int a_row = lane & 15;
    const int a_kh  = lane >> 4;
    const int b_row = (lane & 7) + ((lane >> 4) << 3);
    const int b_kh  = (lane >> 3) & 1;

    auto compute = [&](int stage) {
        const uint32_t sb  = base + stage * STAGE_B;
#pragma unroll
        for (int ks = 0; ks < 2; ks++) {
            const uint32_t ko = ks * 32 + a_kh * 16;
            uint32_t afh[2][4], afl[2][4];
#pragma unroll
            for (int ma = 0; ma < 2; ma++) {
                const uint32_t ro = (uint32_t)(wm * 32 + ma * 16 + a_row) * ROWB;
                ldmx4(afh[ma], sb + OFF_AH + ro + ko);
                ldmx4(afl[ma], sb + OFF_AL + ro + ko);
            }
            const uint32_t bko = ks * 32 + b_kh * 16;
            uint32_t bf[4][4];
#pragma unroll
            for (int nb = 0; nb < 4; nb++)
                ldmx4(bf[nb], sb + OFF_BH +
                      (uint32_t)(wn * 64 + nb * 16 + b_row) * ROWB + bko);
            // pass 1: Ah*Bh ; pass 2: Al*Bh
#pragma unroll
            for (int nb = 0; nb < 4; nb++)
#pragma unroll
                for (int ma = 0; ma < 2; ma++) {
                    mma_h(acc[ma][2 * nb],     afh[ma], bf[nb]);
                    mma_h(acc[ma][2 * nb + 1], afh[ma], bf[nb] + 2);
                    mma_h(acc[ma][2 * nb],     afl[ma], bf[nb]);
                    mma_h(acc[ma][2 * nb + 1], afl[ma], bf[nb] + 2);
                }
            // pass 3: Ah*Bl (reuse bf regs)
#pragma unroll
            for (int nb = 0; nb < 4; nb++)
                ldmx4(bf[nb], sb + OFF_BL +
                      (uint32_t)(wn * 64 + nb * 16 + b_row) * ROWB + bko);
#pragma unroll
            for (int nb = 0; nb < 4; nb++)
#pragma unroll
                for (int ma = 0; ma < 2; ma++) {
                    mma_h(acc[ma][2 * nb],     afh[ma], bf[nb]);
                    mma_h(acc[ma][2 * nb + 1], afh[ma], bf[nb] + 2);
                }
        }
    };

    load_chunk(0, 0);
    for (int i = 0; i < nchunk; i++) {
        if (i + 1 < nchunk) {
            load_chunk(i + 1, (i + 1) & 1);
            asm volatile("cp.async.wait_group 1;" ::: "memory");
        } else {
            asm volatile("cp.async.wait_group 0;" ::: "memory");
        }
        __syncthreads();
        compute(i & 1);
        __syncthreads();
    }

    if (MODE == 0) {
#pragma unroll
        for (int ma = 0; ma < 2; ma++) {
            const int r0 = bm + wm * 32 + ma * 16 + (lane >> 2);
            const int cb = bn + wn * 64 + 2 * (lane & 3);
#pragma unroll
            for (int half = 0; half < 2; half++) {
                float* crow = C + (size_t)(r0 + half * 8) * N + cb;
#pragma unroll
                for (int na = 0; na < 8; na++)
                    *(float2*)(crow + na * 8) =
                        make_float2(acc[ma][na][half * 2], acc[ma][na][half * 2 + 1]);
            }
        }
    } else {
        // fused RoPE + hi/lo split + [h][s][d] scatter; each warp = one head
        const int hh = (bn + wn * 64) >> 6;
#pragma unroll
        for (int ma = 0; ma < 2; ma++) {
#pragma unroll
            for (int half = 0; half < 2; half++) {
                const int s = bm + wm * 32 + ma * 16 + (lane >> 2) + half * 8;
                if (hh < NH + NKV) {
#pragma unroll
                    for (int na = 0; na < 4; na++) {
                        const int d = na * 8 + 2 * (lane & 3);
                        float2 cl = *(const float2*)(cosb + s * HD + d);
                        float2 sl = *(const float2*)(sinb + s * HD + d);
                        float2 ch = *(const float2*)(cosb + s * HD + d + 32);
                        float2 sh = *(const float2*)(sinb + s * HD + d + 32);
                        float v0 = acc[ma][na][half * 2];
                        float v1 = acc[ma][na][half * 2 + 1];
                        float w0 = acc[ma][na + 4][half * 2];
                        float w1 = acc[ma][na + 4][half * 2 + 1];
                        float r0 = v0 * cl.x - w0 * sl.x;
                        float r1 = v1 * cl.y - w1 * sl.y;
                        float u0 = w0 * ch.x + v0 * sh.x;
                        float u1 = w1 * ch.y + v1 * sh.y;
                        uint32_t hp, lp, hp2, lp2;
                        split2(r0, r1, hp, lp);
                        split2(u0, u1, hp2, lp2);
                        if (hh < NH) {
                            size_t a0 = ((size_t)(hh * S_LEN + s) << 6) + d;
                            *(uint32_t*)(g_qhh + a0) = hp;
                            *(uint32_t*)(g_qhl + a0) = lp;
                            *(uint32_t*)(g_qhh + a0 + 32) = hp2;
                            *(uint32_t*)(g_qhl + a0 + 32) = lp2;
                        } else {
                            size_t a0 = ((size_t)((hh - NH) * S_LEN + s) << 6) + d;
                            *(uint32_t*)(g_khh + a0) = hp;
                            *(uint32_t*)(g_khl + a0) = lp;
                            *(uint32_t*)(g_khh + a0 + 32) = hp2;
                            *(uint32_t*)(g_khl + a0 + 32) = lp2;
                        }
                    }
                } else {
#pragma unroll
                    for (int na = 0; na < 8; na++) {
                        const int d = na * 8 + 2 * (lane & 3);
                        uint32_t hp, lp;
                        split2(acc[ma][na][half * 2], acc[ma][na][half * 2 + 1],
                               hp, lp);
                        size_t a0 = ((size_t)((hh - NH - NKV) * S_LEN + s) << 6) + d;
                        *(uint32_t*)(g_vhh + a0) = hp;
                        *(uint32_t*)(g_vhl + a0) = lp;
                    }
                }
            }
        }
    }
}

// ============================================================================
// fp32 -> (hi, lo) fp16 split, float4-vectorized
// ============================================================================
__global__ __launch_bounds__(256) void split_h(const float* __restrict__ in,
                                               __half* __restrict__ hi,
                                               __half* __restrict__ lo, int n4) {
    int i = blockIdx.x * 256 + threadIdx.x;
    if (i >= n4) return;
    float4 v = ((const float4*)in)[i];
    uint32_t h0, l0, h1, l1;
    split2(v.x, v.y, h0, l0);
    split2(v.z, v.w, h1, l1);
    ((uint2*)hi)[i] = make_uint2(h0, h1);
    ((uint2*)lo)[i] = make_uint2(l0, l1);
}

// ============================================================================
// fp16 split-precision (3-pass) flash attention — round-5/12 proven version.
// grid (16 qb, 32 h); 256 thr = 8 warps x 16 q-rows. Q tile 128, KV tiles 64.
// ============================================================================
#define AROWB 144
#define AQ_B   (128 * AROWB)
#define AKV_B  (64 * AROWB)
#define AST_B  (4 * AKV_B)
#define ATTN_SMEM (2 * AQ_B + 2 * AST_B) // 110592

__global__ __launch_bounds__(256, 1) void flash_attn_s() {
    extern __shared__ __align__(128) char dsm[];
    const uint32_t base = smem_u32(dsm);
    const uint32_t sQh = base;
    const uint32_t sQl = base + AQ_B;
    const uint32_t ringb = base + 2 * AQ_B;

    const int qb = 15 - (int)blockIdx.x;     // heavy CTAs first
    const int h  = blockIdx.y;
    const __half* Qhg = g_qhh + (size_t)(h * S_LEN + qb * 128) * HD;
    const __half* Qlg = g_qhl + (size_t)(h * S_LEN + qb * 128) * HD;
    const size_t kvo = (size_t)((h >> 2) * S_LEN) * HD;
    const __half* Khg = g_khh + kvo;
    const __half* Klg = g_khl + kvo;
    const __half* Vhg = g_vhh + kvo;
    const __half* Vlg = g_vhl + kvo;

    const int tid = threadIdx.x;
    const int wq = tid >> 5;
    const int lane = tid & 31;

#pragma unroll
    for (int i = 0; i < 4; i++) {
        int c = tid + i * 256;
        int r = c >> 3, c8 = c & 7;
        cp16(sQh + r * AROWB + c8 * 16, Qhg + r * HD + c8 * 8);
        cp16(sQl + r * AROWB + c8 * 16, Qlg + r * HD + c8 * 8);
    }
    CP_COMMIT();

    auto load_kv = [&](int kb, int st) {
        const uint32_t sb = ringb + st * AST_B;
#pragma unroll
        for (int i = 0; i < 2; i++) {
            int c = tid + i * 256;
            int r = c >> 3, c8 = c & 7;
            const size_t go = (size_t)(kb * 64 + r) * HD + c8 * 8;
            const uint32_t so = r * AROWB + c8 * 16;
            cp16(sb + so,             Khg + go);
            cp16(sb + AKV_B + so,     Klg + go);
            cp16(sb + 2 * AKV_B + so, Vhg + go);
            cp16(sb + 3 * AKV_B + so, Vlg + go);
        }
        CP_COMMIT();
    };

    const int a_row = lane & 15;
    const int a_kh  = lane >> 4;
    const int b_row = (lane & 7) + ((lane >> 4) << 3);
    const int b_kh  = (lane >> 3) & 1;
    const int v_row = (lane & 7) + ((lane >> 3) & 1) * 8;
    const int v_nh  = (lane >> 4) * 8;

    uint32_t qah[4][4], qal[4][4];
    float oacc[8][4];
    float m_lo = -1e30f, m_hi = -1e30f, l_lo = 0.f, l_hi = 0.f;
#pragma unroll
    for (int a = 0; a < 8; a++)
#pragma unroll
        for (int r = 0; r < 4; r++) oacc[a][r] = 0.f;

    const float sscale = 0.125f * 1.44269504f;
    const int row_lo = qb * 128 + wq * 16 + (lane >> 2);
    const int nkb = 2 * qb + 2;

    load_kv(0, 0);

    for (int i = 0; i < nkb; i++) {
        const int st = i & 1;
        if (i + 1 < nkb) {
            load_kv(i + 1, st ^ 1);
            asm volatile("cp.async.wait_group 1;" ::: "memory");
        } else {
            asm volatile("cp.async.wait_group 0;" ::: "memory");
        }
        __syncthreads();

        if (i == 0) {
#pragma unroll
            for (int ka = 0; ka < 4; ka++) {
                const uint32_t qo = (uint32_t)(wq * 16 + a_row) * AROWB +
                                    ka * 32 + a_kh * 16;
                ldmx4(qah[ka], sQh + qo);
                ldmx4(qal[ka], sQl + qo);
            }
        }

        const uint32_t sKh = ringb + st * AST_B;
        const uint32_t sKl = sKh + AKV_B;
        const uint32_t sVh = sKh + 2 * AKV_B;
        const uint32_t sVl = sKh + 3 * AKV_B;

        // ---- S = Q K^T  (3-pass) ----
        float sacc[8][4];
#pragma unroll
        for (int a = 0; a < 8; a++)
#pragma unroll
            for (int r = 0; r < 4; r++) sacc[a][r] = 0.f;
#pragma unroll
        for (int ka = 0; ka < 4; ka++) {
            const uint32_t bko = ka * 32 + b_kh * 16;
#pragma unroll
            for (int nb = 0; nb < 4; nb++) {
                const uint32_t ro = (uint32_t)(nb * 16 + b_row) * AROWB + bko;
                uint32_t bh[4], bl[4];
                ldmx4(bh, sKh + ro);
                ldmx4(bl, sKl + ro);
                mma_h(sacc[2 * nb],     qah[ka], bh);
                mma_h(sacc[2 * nb + 1], qah[ka], bh + 2);
                mma_h(sacc[2 * nb],     qah[ka], bl);
                mma_h(sacc[2 * nb + 1], qah[ka], bl + 2);
                mma_h(sacc[2 * nb],     qal[ka], bh);
                mma_h(sacc[2 * nb + 1], qal[ka], bh + 2);
            }
        }

        // ---- scale + causal mask ----
        const bool need_mask = (i * 64 + 63) > (qb * 128 + wq * 16);
        if (need_mask) {
#pragma unroll
            for (int a = 0; a < 8; a++) {
                const int colb = i * 64 + a * 8 + 2 * (lane & 3);
#pragma unroll
                for (int r = 0; r < 4; r++) {
                    const int col = colb + (r & 1);
                    const int row = row_lo + (r >> 1) * 8;
                    sacc[a][r] = (col > row) ? -1e30f : sacc[a][r] * sscale;
                }
            }
        } else {
#pragma unroll
            for (int a = 0; a < 8; a++)
#pragma unroll
                for (int r = 0; r < 4; r++) sacc[a][r] *= sscale;
        }

        // ---- online softmax ----
        float tmlo = -1e30f, tmhi = -1e30f;
#pragma unroll
        for (int a = 0; a < 8; a++) {
            tmlo = fmaxf(tmlo, fmaxf(sacc[a][0], sacc[a][1]));
            tmhi = fmaxf(tmhi, fmaxf(sacc[a][2], sacc[a][3]));
        }
#pragma unroll
        for (int off = 1; off <= 2; off <<= 1) {
            tmlo = fmaxf(tmlo, __shfl_xor_sync(0xffffffffu, tmlo, off));
            tmhi = fmaxf(tmhi, __shfl_xor_sync(0xffffffffu, tmhi, off));
        }
        const float mn_lo = fmaxf(m_lo, tmlo);
        const float mn_hi = fmaxf(m_hi, tmhi);
        const float corr_lo = ex2(m_lo - mn_lo);
        const float corr_hi = ex2(m_hi - mn_hi);
        m_lo = mn_lo; m_hi = mn_hi;

        float rs_lo = 0.f, rs_hi = 0.f;
#pragma unroll
        for (int a = 0; a < 8; a++) {
            sacc[a][0] = ex2(sacc[a][0] - mn_lo);
            sacc[a][1] = ex2(sacc[a][1] - mn_lo);
            sacc[a][2] = ex2(sacc[a][2] - mn_hi);
            sacc[a][3] = ex2(sacc[a][3] - mn_hi);
            rs_lo += sacc[a][0] + sacc[a][1];
            rs_hi += sacc[a][2] + sacc[a][3];
        }
#pragma unroll
        for (int off = 1; off <= 2; off <<= 1) {
            rs_lo += __shfl_xor_sync(0xffffffffu, rs_lo, off);
            rs_hi += __shfl_xor_sync(0xffffffffu, rs_hi, off);
        }
        l_lo = l_lo * corr_lo + rs_lo;
        l_hi = l_hi * corr_hi + rs_hi;
#pragma unroll
        for (int a = 0; a < 8; a++) {
            oacc[a][0] *= corr_lo; oacc[a][1] *= corr_lo;
            oacc[a][2] *= corr_hi; oacc[a][3] *= corr_hi;
        }

        // ---- O += P V  (3-pass) ----
#pragma unroll
        for (int ka = 0; ka < 4; ka++) {
            uint32_t pah[4], pal[4];
            split2(sacc[2 * ka][0],     sacc[2 * ka][1],     pah[0], pal[0]);
            split2(sacc[2 * ka][2],     sacc[2 * ka][3],     pah[1], pal[1]);
            split2(sacc[2 * ka + 1][0], sacc[2 * ka + 1][1], pah[2], pal[2]);
            split2(sacc[2 * ka + 1][2], sacc[2 * ka + 1][3], pah[3], pal[3]);
#pragma unroll
            for (int nd = 0; nd < 4; nd++) {
                const uint32_t vo = (uint32_t)(ka * 16 + v_row) * AROWB +
                                    (uint32_t)(nd * 16 + v_nh) * 2;
                uint32_t vh[4], vl[4];
                ldmx4t(vh, sVh + vo);
                ldmx4t(vl, sVl + vo);
                mma_h(oacc[2 * nd],     pah, vh);
                mma_h(oacc[2 * nd + 1], pah, vh + 2);
                mma_h(oacc[2 * nd],     pah, vl);
                mma_h(oacc[2 * nd + 1], pah, vl + 2);
                mma_h(oacc[2 * nd],     pal, vh);
                mma_h(oacc[2 * nd + 1], pal, vh + 2);
            }
        }
        __syncthreads();
    }

    // ---- normalize + write split fp16 to g_ahh/g_ahl [s][h*64+d] ----
    const float inv_lo = 1.f / l_lo;
    const float inv_hi = 1.f / l_hi;
    const int srow_lo = qb * 128 + wq * 16 + (lane >> 2);
#pragma unroll
    for (int a = 0; a < 8; a++) {
        const int col = h * 64 + a * 8 + 2 * (lane & 3);
        uint32_t hp, lp;
        split2(oacc[a][0] * inv_lo, oacc[a][1] * inv_lo, hp, lp);
        *(uint32_t*)(g_ahh + (size_t)srow_lo * HID + col) = hp;
        *(uint32_t*)(g_ahl + (size_t)srow_lo * HID + col) = lp;
        split2(oacc[a][2] * inv_hi, oacc[a][3] * inv_hi, hp, lp);
        *(uint32_t*)(g_ahh + (size_t)(srow_lo + 8) * HID + col) = hp;
        *(uint32_t*)(g_ahl + (size_t)(srow_lo + 8) * HID + col) = lp;
    }
}

// =====================================================================
extern "C" void kernel_launch(void* const* d_in, const int* in_sizes, int n_in,
                              void* d_out, int out_size) {
    const float* x     = (const float*)d_in[0];
    const float* cosb  = (const float*)d_in[1];
    const float* sinb  = (const float*)d_in[2];
    const float* w_qkv = (const float*)d_in[3];
    const float* w_out = (const float*)d_in[4];
    float* out = (float*)d_out;

    __half *xh, *xl, *wqh, *wql, *woh, *wol, *ahh, *ahl;
    cudaGetSymbolAddress((void**)&xh, g_xh);
    cudaGetSymbolAddress((void**)&xl, g_xl);
    cudaGetSymbolAddress((void**)&wqh, g_wqh);
    cudaGetSymbolAddress((void**)&wql, g_wql);
    cudaGetSymbolAddress((void**)&woh, g_woh);
    cudaGetSymbolAddress((void**)&wol, g_wol);
    cudaGetSymbolAddress((void**)&ahh, g_ahh);
    cudaGetSymbolAddress((void**)&ahl, g_ahl);

    cudaFuncSetAttribute(gemm_hs<0>, cudaFuncAttributeMaxDynamicSharedMemorySize,
                         GEMM_SMEM);
    cudaFuncSetAttribute(gemm_hs<1>, cudaFuncAttributeMaxDynamicSharedMemorySize,
                         GEMM_SMEM);
    cudaFuncSetAttribute(flash_attn_s, cudaFuncAttributeMaxDynamicSharedMemorySize,
                         ATTN_SMEM);

    // 0) fp32 -> fp16 hi/lo splits
    split_h<<<(S_LEN * HID / 4 + 255) / 256, 256>>>(x, xh, xl, S_LEN * HID / 4);
    split_h<<<(QKV_OUT * HID / 4 + 255) / 256, 256>>>(w_qkv, wqh, wql,
                                                      QKV_OUT * HID / 4);
    split_h<<<(HID * HID / 4 + 255) / 256, 256>>>(w_out, woh, wol, HID * HID / 4);

    // 1) QKV projection + fused RoPE/split/transpose  (N tiles of 256)
    gemm_hs<1><<<dim3(QKV_OUT / 256, S_LEN / 128), 512, GEMM_SMEM>>>(
        xh, xl, wqh, wql, nullptr, cosb, sinb, QKV_OUT, HID);
    // 2) 3-pass fp16 split flash attention
    flash_attn_s<<<dim3(16, NH), 256, ATTN_SMEM>>>();
    // 3) out-projection, fp32 out
    gemm_hs<0><<<dim3(HID / 256, S_LEN / 128), 512, GEMM_SMEM>>>(
        ahh, ahl, woh, wol, out, nullptr, nullptr, HID, NH * HD);
}

// round 14
// speedup vs baseline: 1.1973x; 1.1973x over previous
#include <cuda_runtime.h>
#include <cuda_fp16.h>
#include <cstdint>

#define S_LEN 2048
#define HID 2048
#define NH 32
#define NKV 8
#define HD 64
#define QKV_OUT 3072   // (32 + 2*8) * 64

// ---------------- scratch (static device globals; no allocation) ----------------
__device__ __align__(16) __half g_xh[S_LEN * HID],  g_xl[S_LEN * HID];
__device__ __align__(16) __half g_wqh[QKV_OUT * HID], g_wql[QKV_OUT * HID];
__device__ __align__(16) __half g_woh[HID * HID],   g_wol[HID * HID];
__device__ __align__(16) __half g_qhh[NH * S_LEN * HD],  g_qhl[NH * S_LEN * HD];
__device__ __align__(16) __half g_khh[NKV * S_LEN * HD], g_khl[NKV * S_LEN * HD];
__device__ __align__(16) __half g_vhh[NKV * S_LEN * HD], g_vhl[NKV * S_LEN * HD];
__device__ __align__(16) __half g_ahh[S_LEN * HID], g_ahl[S_LEN * HID];

// ============================ helpers ============================
__device__ __forceinline__ uint32_t smem_u32(const void* p) {
    uint32_t a;
    asm("{ .reg .u64 t; cvta.to.shared.u64 t, %1; cvt.u32.u64 %0, t; }"
        : "=r"(a) : "l"(p));
    return a;
}
__device__ __forceinline__ void cp16(uint32_t s, const void* g) {
    asm volatile("cp.async.cg.shared.global [%0], [%1], 16;" :: "r"(s), "l"(g));
}
#define CP_COMMIT() asm volatile("cp.async.commit_group;" ::: "memory")

__device__ __forceinline__ void ldmx4(uint32_t* r, uint32_t addr) {
    asm volatile("ldmatrix.sync.aligned.m8n8.x4.shared.b16 {%0,%1,%2,%3}, [%4];"
                 : "=r"(r[0]), "=r"(r[1]), "=r"(r[2]), "=r"(r[3]) : "r"(addr));
}
__device__ __forceinline__ void ldmx4t(uint32_t* r, uint32_t addr) {
    asm volatile("ldmatrix.sync.aligned.m8n8.x4.trans.shared.b16 {%0,%1,%2,%3}, [%4];"
                 : "=r"(r[0]), "=r"(r[1]), "=r"(r[2]), "=r"(r[3]) : "r"(addr));
}
__device__ __forceinline__ void mma_h(float* d, const uint32_t* a,
                                      const uint32_t* b) {
    asm volatile(
        "mma.sync.aligned.m16n8k16.row.col.f32.f16.f16.f32 "
        "{%0,%1,%2,%3}, {%4,%5,%6,%7}, {%8,%9}, {%0,%1,%2,%3};"
        : "+f"(d[0]), "+f"(d[1]), "+f"(d[2]), "+f"(d[3])
        : "r"(a[0]), "r"(a[1]), "r"(a[2]), "r"(a[3]), "r"(b[0]), "r"(b[1]));
}
__device__ __forceinline__ float ex2(float x) {
    float y;
    asm("ex2.approx.ftz.f32 %0, %1;" : "=f"(y) : "f"(x));
    return y;
}
__device__ __forceinline__ void split2(float a, float b, uint32_t& hp, uint32_t& lp) {
    __half ha = __float2half_rn(a), hb = __float2half_rn(b);
    hp = (uint32_t)__half_as_ushort(ha) | ((uint32_t)__half_as_ushort(hb) << 16);
    __half la = __float2half_rn(a - __half2float(ha));
    __half lb = __float2half_rn(b - __half2float(hb));
    lp = (uint32_t)__half_as_ushort(la) | ((uint32_t)__half_as_ushort(lb) << 16);
}

// ============================================================================
// fp16 split-precision GEMM (3-pass), fp32 accum — round-12 champion verbatim.
// BK=32, 2-stage cp.async. 128x128 CTA tile, 8 warps (4x2), warp 32x64.
// MODE 0: fp32 C out.  MODE 1: fused RoPE + hi/lo split + [h][s][d] scatter.
// ============================================================================
#define BK 32
#define ROWB 80
#define TILE_B (128 * ROWB)             // 10240
#define STAGE_B (4 * TILE_B)            // Ah, Al, Bh, Bl = 40960
#define GEMM_SMEM (2 * STAGE_B)         // 81920

template <int MODE>
__global__ __launch_bounds__(256, 2) void gemm_hs(
    const __half* __restrict__ Ah, const __half* __restrict__ Al,
    const __half* __restrict__ Bh, const __half* __restrict__ Bl,
    float* __restrict__ C, const float* __restrict__ cosb,
    const float* __restrict__ sinb, int N, int K) {
    extern __shared__ __align__(128) char dsm[];
    const uint32_t base = smem_u32(dsm);

    const int tid = threadIdx.x;
    const int wid = tid >> 5;
    const int lane = tid & 31;
    const int wm = wid >> 1;
    const int wn = wid & 1;
    const int bm = blockIdx.y * 128;
    const int bn = blockIdx.x * 128;
    const int nchunk = K / BK;

    float acc[2][8][4];
#pragma unroll
    for (int i = 0; i < 2; i++)
#pragma unroll
        for (int j = 0; j < 8; j++)
#pragma unroll
            for (int k = 0; k < 4; k++) acc[i][j][k] = 0.f;

    auto load_chunk = [&](int chunk, int stage) {
        const int k0 = chunk * BK;
        const uint32_t sb = base + stage * STAGE_B;
#pragma unroll
        for (int t = 0; t < 4; t++) {
            const __half* src = (t == 0) ? Ah : (t == 1) ? Al : (t == 2) ? Bh : Bl;
            const int rowbase = (t < 2) ? bm : bn;
            const uint32_t tb = sb + t * TILE_B;
#pragma unroll
            for (int i = 0; i < 2; i++) {
                int c = tid + i * 256;
                int r = c >> 2;
                int cc = c & 3;
                cp16(tb + r * ROWB + cc * 16,
                     src + (size_t)(rowbase + r) * K + k0 + cc * 8);
            }
        }
        CP_COMMIT();
    };

    const int a_row = lane & 15;
    const int a_kh  = lane >> 4;
    const int b_row = (lane & 7) + ((lane >> 4) << 3);
    const int b_kh  = (lane >> 3) & 1;

    auto compute = [&](int stage) {
        const uint32_t sb  = base + stage * STAGE_B;
        const uint32_t sAh = sb;
        const uint32_t sAl = sb + TILE_B;
        const uint32_t sBh = sb + 2 * TILE_B;
        const uint32_t sBl = sb + 3 * TILE_B;
#pragma unroll
        for (int ks = 0; ks < 2; ks++) {
            const uint32_t ko = ks * 32 + a_kh * 16;
            uint32_t afh[2][4], afl[2][4];
#pragma unroll
            for (int ma = 0; ma < 2; ma++) {
                const uint32_t ro = (uint32_t)(wm * 32 + ma * 16 + a_row) * ROWB;
                ldmx4(afh[ma], sAh + ro + ko);
                ldmx4(afl[ma], sAl + ro + ko);
            }
            const uint32_t bko = ks * 32 + b_kh * 16;
#pragma unroll
            for (int nb = 0; nb < 4; nb++) {
                uint32_t bf[4];
                ldmx4(bf, sBh + (uint32_t)(wn * 64 + nb * 16 + b_row) * ROWB + bko);
#pragma unroll
                for (int ma = 0; ma < 2; ma++) {
                    mma_h(acc[ma][2 * nb],     afh[ma], bf);
                    mma_h(acc[ma][2 * nb + 1], afh[ma], bf + 2);
                    mma_h(acc[ma][2 * nb],     afl[ma], bf);
                    mma_h(acc[ma][2 * nb + 1], afl[ma], bf + 2);
                }
            }
#pragma unroll
            for (int nb = 0; nb < 4; nb++) {
                uint32_t bf[4];
                ldmx4(bf, sBl + (uint32_t)(wn * 64 + nb * 16 + b_row) * ROWB + bko);
#pragma unroll
                for (int ma = 0; ma < 2; ma++) {
                    mma_h(acc[ma][2 * nb],     afh[ma], bf);
                    mma_h(acc[ma][2 * nb + 1], afh[ma], bf + 2);
                }
            }
        }
    };

    load_chunk(0, 0);
    for (int i = 0; i < nchunk; i++) {
        if (i + 1 < nchunk) {
            load_chunk(i + 1, (i + 1) & 1);
            asm volatile("cp.async.wait_group 1;" ::: "memory");
        } else {
            asm volatile("cp.async.wait_group 0;" ::: "memory");
        }
        __syncthreads();
        compute(i & 1);
        __syncthreads();
    }

    if (MODE == 0) {
#pragma unroll
        for (int ma = 0; ma < 2; ma++) {
            const int r0 = bm + wm * 32 + ma * 16 + (lane >> 2);
            const int cb = bn + wn * 64 + 2 * (lane & 3);
#pragma unroll
            for (int half = 0; half < 2; half++) {
                float* crow = C + (size_t)(r0 + half * 8) * N + cb;
#pragma unroll
                for (int na = 0; na < 8; na++)
                    *(float2*)(crow + na * 8) =
                        make_float2(acc[ma][na][half * 2], acc[ma][na][half * 2 + 1]);
            }
        }
    } else {
        // fused RoPE + hi/lo split + [h][s][d] scatter
        const int hh = (bn + wn * 64) >> 6;
#pragma unroll
        for (int ma = 0; ma < 2; ma++) {
#pragma unroll
            for (int half = 0; half < 2; half++) {
                const int s = bm + wm * 32 + ma * 16 + (lane >> 2) + half * 8;
                if (hh < NH + NKV) {
#pragma unroll
                    for (int na = 0; na < 4; na++) {
                        const int d = na * 8 + 2 * (lane & 3);
                        float2 cl = *(const float2*)(cosb + s * HD + d);
                        float2 sl = *(const float2*)(sinb + s * HD + d);
                        float2 ch = *(const float2*)(cosb + s * HD + d + 32);
                        float2 sh = *(const float2*)(sinb + s * HD + d + 32);
                        float v0 = acc[ma][na][half * 2];
                        float v1 = acc[ma][na][half * 2 + 1];
                        float w0 = acc[ma][na + 4][half * 2];
                        float w1 = acc[ma][na + 4][half * 2 + 1];
                        float r0 = v0 * cl.x - w0 * sl.x;
                        float r1 = v1 * cl.y - w1 * sl.y;
                        float u0 = w0 * ch.x + v0 * sh.x;
                        float u1 = w1 * ch.y + v1 * sh.y;
                        uint32_t hp, lp, hp2, lp2;
                        split2(r0, r1, hp, lp);
                        split2(u0, u1, hp2, lp2);
                        if (hh < NH) {
                            size_t a0 = ((size_t)(hh * S_LEN + s) << 6) + d;
                            *(uint32_t*)(g_qhh + a0) = hp;
                            *(uint32_t*)(g_qhl + a0) = lp;
                            *(uint32_t*)(g_qhh + a0 + 32) = hp2;
                            *(uint32_t*)(g_qhl + a0 + 32) = lp2;
                        } else {
                            size_t a0 = ((size_t)((hh - NH) * S_LEN + s) << 6) + d;
                            *(uint32_t*)(g_khh + a0) = hp;
                            *(uint32_t*)(g_khl + a0) = lp;
                            *(uint32_t*)(g_khh + a0 + 32) = hp2;
                            *(uint32_t*)(g_khl + a0 + 32) = lp2;
                        }
                    }
                } else {
#pragma unroll
                    for (int na = 0; na < 8; na++) {
                        const int d = na * 8 + 2 * (lane & 3);
                        uint32_t hp, lp;
                        split2(acc[ma][na][half * 2], acc[ma][na][half * 2 + 1],
                               hp, lp);
                        size_t a0 = ((size_t)((hh - NH - NKV) * S_LEN + s) << 6) + d;
                        *(uint32_t*)(g_vhh + a0) = hp;
                        *(uint32_t*)(g_vhl + a0) = lp;
                    }
                }
            }
        }
    }
}

// ============================================================================
// fp32 -> (hi, lo) fp16 split — ONE launch for x, w_qkv, w_out (range dispatch)
// ============================================================================
#define N4_X  (S_LEN * HID / 4)
#define N4_WQ (QKV_OUT * HID / 4)
#define N4_WO (HID * HID / 4)
#define N4_ALL (N4_X + N4_WQ + N4_WO)

__global__ __launch_bounds__(256) void split_all(
    const float* __restrict__ x, const float* __restrict__ wq,
    const float* __restrict__ wo) {
    int i = blockIdx.x * 256 + threadIdx.x;
    if (i >= N4_ALL) return;
    const float* in;
    __half *hi, *lo;
    int j = i;
    if (j < N4_X) { in = x; hi = g_xh; lo = g_xl; }
    else if ((j -= N4_X) < N4_WQ) { in = wq; hi = g_wqh; lo = g_wql; }
    else { j -= N4_WQ; in = wo; hi = g_woh; lo = g_wol; }
    float4 v = ((const float4*)in)[j];
    uint32_t h0, l0, h1, l1;
    split2(v.x, v.y, h0, l0);
    split2(v.z, v.w, h1, l1);
    ((uint2*)hi)[j] = make_uint2(h0, h1);
    ((uint2*)lo)[j] = make_uint2(l0, l1);
}

// ============================================================================
// fp16 split-precision (3-pass) flash attention, causal, GQA.
// NEW: Q tile 64 rows, 128 threads (4 warps x 16 rows), smem 92160 ->
// 2 CTAs/SM so one CTA's MMA phases overlap the other's softmax phases.
// grid (32 qb, 32 h). KV tiles 64 keys, 2-stage ring. Math unchanged.
// ============================================================================
#define AROWB 144
#define AQ_B   (64 * AROWB)              // 9216
#define AKV_B  (64 * AROWB)              // 9216
#define AST_B  (4 * AKV_B)               // Kh,Kl,Vh,Vl = 36864
#define ATTN_SMEM (2 * AQ_B + 2 * AST_B) // 92160

__global__ __launch_bounds__(128, 2) void flash_attn_s() {
    extern __shared__ __align__(128) char dsm[];
    const uint32_t base = smem_u32(dsm);
    const uint32_t sQh = base;
    const uint32_t sQl = base + AQ_B;
    const uint32_t ringb = base + 2 * AQ_B;

    const int qb = 31 - (int)blockIdx.x;     // heavy CTAs first
    const int h  = blockIdx.y;
    const __half* Qhg = g_qhh + (size_t)(h * S_LEN + qb * 64) * HD;
    const __half* Qlg = g_qhl + (size_t)(h * S_LEN + qb * 64) * HD;
    const size_t kvo = (size_t)((h >> 2) * S_LEN) * HD;
    const __half* Khg = g_khh + kvo;
    const __half* Klg = g_khl + kvo;
    const __half* Vhg = g_vhh + kvo;
    const __half* Vlg = g_vhl + kvo;

    const int tid = threadIdx.x;
    const int wq = tid >> 5;                 // 0..3, 16 q-rows each
    const int lane = tid & 31;

    // ---- Q hi/lo loads: 64 rows x 128B each = 512 cp16 per tile ----
#pragma unroll
    for (int i = 0; i < 4; i++) {
        int c = tid + i * 128;
        int r = c >> 3, c8 = c & 7;
        cp16(sQh + r * AROWB + c8 * 16, Qhg + r * HD + c8 * 8);
        cp16(sQl + r * AROWB + c8 * 16, Qlg + r * HD + c8 * 8);
    }
    CP_COMMIT();

    auto load_kv = [&](int kb, int st) {
        const uint32_t sb = ringb + st * AST_B;
#pragma unroll
        for (int i = 0; i < 4; i++) {
            int c = tid + i * 128;
            int r = c >> 3, c8 = c & 7;
            const size_t go = (size_t)(kb * 64 + r) * HD + c8 * 8;
            const uint32_t so = r * AROWB + c8 * 16;
            cp16(sb + so,             Khg + go);
            cp16(sb + AKV_B + so,     Klg + go);
            cp16(sb + 2 * AKV_B + so, Vhg + go);
            cp16(sb + 3 * AKV_B + so, Vlg + go);
        }
        CP_COMMIT();
    };

    const int a_row = lane & 15;
    const int a_kh  = lane >> 4;
    const int b_row = (lane & 7) + ((lane >> 4) << 3);
    const int b_kh  = (lane >> 3) & 1;
    const int v_row = (lane & 7) + ((lane >> 3) & 1) * 8;
    const int v_nh  = (lane >> 4) * 8;

    uint32_t qah[4][4], qal[4][4];
    float oacc[8][4];
    float m_lo = -1e30f, m_hi = -1e30f, l_lo = 0.f, l_hi = 0.f;
#pragma unroll
    for (int a = 0; a < 8; a++)
#pragma unroll
        for (int r = 0; r < 4; r++) oacc[a][r] = 0.f;

    const float sscale = 0.125f * 1.44269504f;
    const int row_lo = qb * 64 + wq * 16 + (lane >> 2);
    const int nkb = qb + 1;

    load_kv(0, 0);

    for (int i = 0; i < nkb; i++) {
        const int st = i & 1;
        if (i + 1 < nkb) {
            load_kv(i + 1, st ^ 1);
            asm volatile("cp.async.wait_group 1;" ::: "memory");
        } else {
            asm volatile("cp.async.wait_group 0;" ::: "memory");
        }
        __syncthreads();

        if (i == 0) {
#pragma unroll
            for (int ka = 0; ka < 4; ka++) {
                const uint32_t qo = (uint32_t)(wq * 16 + a_row) * AROWB +
                                    ka * 32 + a_kh * 16;
                ldmx4(qah[ka], sQh + qo);
                ldmx4(qal[ka], sQl + qo);
            }
        }

        const uint32_t sKh = ringb + st * AST_B;
        const uint32_t sKl = sKh + AKV_B;
        const uint32_t sVh = sKh + 2 * AKV_B;
        const uint32_t sVl = sKh + 3 * AKV_B;

        // ---- S = Q K^T  (3-pass) ----
        float sacc[8][4];
#pragma unroll
        for (int a = 0; a < 8; a++)
#pragma unroll
            for (int r = 0; r < 4; r++) sacc[a][r] = 0.f;
#pragma unroll
        for (int ka = 0; ka < 4; ka++) {
            const uint32_t bko = ka * 32 + b_kh * 16;
#pragma unroll
            for (int nb = 0; nb < 4; nb++) {
                const uint32_t ro = (uint32_t)(nb * 16 + b_row) * AROWB + bko;
                uint32_t bh[4], bl[4];
                ldmx4(bh, sKh + ro);
                ldmx4(bl, sKl + ro);
                mma_h(sacc[2 * nb],     qah[ka], bh);
                mma_h(sacc[2 * nb + 1], qah[ka], bh + 2);
                mma_h(sacc[2 * nb],     qah[ka], bl);
                mma_h(sacc[2 * nb + 1], qah[ka], bl + 2);
                mma_h(sacc[2 * nb],     qal[ka], bh);
                mma_h(sacc[2 * nb + 1], qal[ka], bh + 2);
            }
        }

        // ---- scale + causal mask (only diagonal block) ----
        const bool need_mask = (i * 64 + 63) > (qb * 64 + wq * 16);
        if (need_mask) {
#pragma unroll
            for (int a = 0; a < 8; a++) {
                const int colb = i * 64 + a * 8 + 2 * (lane & 3);
#pragma unroll
                for (int r = 0; r < 4; r++) {
                    const int col = colb + (r & 1);
                    const int row = row_lo + (r >> 1) * 8;
                    sacc[a][r] = (col > row) ? -1e30f : sacc[a][r] * sscale;
                }
            }
        } else {
#pragma unroll
            for (int a = 0; a < 8; a++)
#pragma unroll
                for (int r = 0; r < 4; r++) sacc[a][r] *= sscale;
        }

        // ---- online softmax ----
        float tmlo = -1e30f, tmhi = -1e30f;
#pragma unroll
        for (int a = 0; a < 8; a++) {
            tmlo = fmaxf(tmlo, fmaxf(sacc[a][0], sacc[a][1]));
            tmhi = fmaxf(tmhi, fmaxf(sacc[a][2], sacc[a][3]));
        }
#pragma unroll
        for (int off = 1; off <= 2; off <<= 1) {
            tmlo = fmaxf(tmlo, __shfl_xor_sync(0xffffffffu, tmlo, off));
            tmhi = fmaxf(tmhi, __shfl_xor_sync(0xffffffffu, tmhi, off));
        }
        const float mn_lo = fmaxf(m_lo, tmlo);
        const float mn_hi = fmaxf(m_hi, tmhi);
        const float corr_lo = ex2(m_lo - mn_lo);
        const float corr_hi = ex2(m_hi - mn_hi);
        m_lo = mn_lo; m_hi = mn_hi;

        float rs_lo = 0.f, rs_hi = 0.f;
#pragma unroll
        for (int a = 0; a < 8; a++) {
            sacc[a][0] = ex2(sacc[a][0] - mn_lo);
            sacc[a][1] = ex2(sacc[a][1] - mn_lo);
            sacc[a][2] = ex2(sacc[a][2] - mn_hi);
            sacc[a][3] = ex2(sacc[a][3] - mn_hi);
            rs_lo += sacc[a][0] + sacc[a][1];
            rs_hi += sacc[a][2] + sacc[a][3];
        }
#pragma unroll
        for (int off = 1; off <= 2; off <<= 1) {
            rs_lo += __shfl_xor_sync(0xffffffffu, rs_lo, off);
            rs_hi += __shfl_xor_sync(0xffffffffu, rs_hi, off);
        }
        l_lo = l_lo * corr_lo + rs_lo;
        l_hi = l_hi * corr_hi + rs_hi;
#pragma unroll
        for (int a = 0; a < 8; a++) {
            oacc[a][0] *= corr_lo; oacc[a][1] *= corr_lo;
            oacc[a][2] *= corr_hi; oacc[a][3] *= corr_hi;
        }

        // ---- O += P V  (3-pass) ----
#pragma unroll
        for (int ka = 0; ka < 4; ka++) {
            uint32_t pah[4], pal[4];
            split2(sacc[2 * ka][0],     sacc[2 * ka][1],     pah[0], pal[0]);
            split2(sacc[2 * ka][2],     sacc[2 * ka][3],     pah[1], pal[1]);
            split2(sacc[2 * ka + 1][0], sacc[2 * ka + 1][1], pah[2], pal[2]);
            split2(sacc[2 * ka + 1][2], sacc[2 * ka + 1][3], pah[3], pal[3]);
#pragma unroll
            for (int nd = 0; nd < 4; nd++) {
                const uint32_t vo = (uint32_t)(ka * 16 + v_row) * AROWB +
                                    (uint32_t)(nd * 16 + v_nh) * 2;
                uint32_t vh[4], vl[4];
                ldmx4t(vh, sVh + vo);
                ldmx4t(vl, sVl + vo);
                mma_h(oacc[2 * nd],     pah, vh);
                mma_h(oacc[2 * nd + 1], pah, vh + 2);
                mma_h(oacc[2 * nd],     pah, vl);
                mma_h(oacc[2 * nd + 1], pah, vl + 2);
                mma_h(oacc[2 * nd],     pal, vh);
                mma_h(oacc[2 * nd + 1], pal, vh + 2);
            }
        }
        __syncthreads();
    }

    // ---- normalize + write split fp16 to g_ahh/g_ahl [s][h*64+d] ----
    const float inv_lo = 1.f / l_lo;
    const float inv_hi = 1.f / l_hi;
    const int srow_lo = qb * 64 + wq * 16 + (lane >> 2);
#pragma unroll
    for (int a = 0; a < 8; a++) {
        const int col = h * 64 + a * 8 + 2 * (lane & 3);
        uint32_t hp, lp;
        split2(oacc[a][0] * inv_lo, oacc[a][1] * inv_lo, hp, lp);
        *(uint32_t*)(g_ahh + (size_t)srow_lo * HID + col) = hp;
        *(uint32_t*)(g_ahl + (size_t)srow_lo * HID + col) = lp;
        split2(oacc[a][2] * inv_hi, oacc[a][3] * inv_hi, hp, lp);
        *(uint32_t*)(g_ahh + (size_t)(srow_lo + 8) * HID + col) = hp;
        *(uint32_t*)(g_ahl + (size_t)(srow_lo + 8) * HID + col) = lp;
    }
}

// =====================================================================
extern "C" void kernel_launch(void* const* d_in, const int* in_sizes, int n_in,
                              void* d_out, int out_size) {
    const float* x     = (const float*)d_in[0];
    const float* cosb  = (const float*)d_in[1];
    const float* sinb  = (const float*)d_in[2];
    const float* w_qkv = (const float*)d_in[3];
    const float* w_out = (const float*)d_in[4];
    float* out = (float*)d_out;

    __half *xh, *xl, *wqh, *wql, *woh, *wol, *ahh, *ahl;
    cudaGetSymbolAddress((void**)&xh, g_xh);
    cudaGetSymbolAddress((void**)&xl, g_xl);
    cudaGetSymbolAddress((void**)&wqh, g_wqh);
    cudaGetSymbolAddress((void**)&wql, g_wql);
    cudaGetSymbolAddress((void**)&woh, g_woh);
    cudaGetSymbolAddress((void**)&wol, g_wol);
    cudaGetSymbolAddress((void**)&ahh, g_ahh);
    cudaGetSymbolAddress((void**)&ahl, g_ahl);

    cudaFuncSetAttribute(gemm_hs<0>, cudaFuncAttributeMaxDynamicSharedMemorySize,
                         GEMM_SMEM);
    cudaFuncSetAttribute(gemm_hs<1>, cudaFuncAttributeMaxDynamicSharedMemorySize,
                         GEMM_SMEM);
    cudaFuncSetAttribute(flash_attn_s, cudaFuncAttributeMaxDynamicSharedMemorySize,
                         ATTN_SMEM);

    // 0) fp32 -> fp16 hi/lo splits (single fused launch)
    split_all<<<(N4_ALL + 255) / 256, 256>>>(x, w_qkv, w_out);

    // 1) QKV projection + fused RoPE/split/transpose
    gemm_hs<1><<<dim3(QKV_OUT / 128, S_LEN / 128), 256, GEMM_SMEM>>>(
        xh, xl, wqh, wql, nullptr, cosb, sinb, QKV_OUT, HID);
    // 2) 3-pass fp16 split flash attention (64-row Q tiles, 2 CTAs/SM)
    flash_attn_s<<<dim3(32, NH), 128, ATTN_SMEM>>>();
    // 3) out-projection, fp32 out
    gemm_hs<0><<<dim3(HID / 128, S_LEN / 128), 256, GEMM_SMEM>>>(
        ahh, ahl, woh, wol, out, nullptr, nullptr, HID, NH * HD);
}

// round 15
// speedup vs baseline: 1.4671x; 1.2254x over previous
#include <cuda_runtime.h>
#include <cuda_fp16.h>
#include <cstdint>

#define S_LEN 2048
#define HID 2048
#define NH 32
#define NKV 8
#define HD 64
#define QKV_OUT 3072   // (32 + 2*8) * 64

// ---------------- scratch (static device globals; no allocation) ----------------
__device__ __align__(16) __half g_xh[S_LEN * HID],  g_xl[S_LEN * HID];
__device__ __align__(16) __half g_wqh[QKV_OUT * HID];
__device__ __align__(16) __half g_woh[HID * HID];
__device__ __align__(16) __half g_qhh[NH * S_LEN * HD],  g_qhl[NH * S_LEN * HD];
__device__ __align__(16) __half g_khh[NKV * S_LEN * HD], g_khl[NKV * S_LEN * HD];
__device__ __align__(16) __half g_vhh[NKV * S_LEN * HD], g_vhl[NKV * S_LEN * HD];
__device__ __align__(16) __half g_ahh[S_LEN * HID], g_ahl[S_LEN * HID];

// ============================ helpers ============================
__device__ __forceinline__ uint32_t smem_u32(const void* p) {
    uint32_t a;
    asm("{ .reg .u64 t; cvta.to.shared.u64 t, %1; cvt.u32.u64 %0, t; }"
        : "=r"(a) : "l"(p));
    return a;
}
__device__ __forceinline__ void cp16(uint32_t s, const void* g) {
    asm volatile("cp.async.cg.shared.global [%0], [%1], 16;" :: "r"(s), "l"(g));
}
#define CP_COMMIT() asm volatile("cp.async.commit_group;" ::: "memory")

__device__ __forceinline__ void ldmx4(uint32_t* r, uint32_t addr) {
    asm volatile("ldmatrix.sync.aligned.m8n8.x4.shared.b16 {%0,%1,%2,%3}, [%4];"
                 : "=r"(r[0]), "=r"(r[1]), "=r"(r[2]), "=r"(r[3]) : "r"(addr));
}
__device__ __forceinline__ void ldmx4t(uint32_t* r, uint32_t addr) {
    asm volatile("ldmatrix.sync.aligned.m8n8.x4.trans.shared.b16 {%0,%1,%2,%3}, [%4];"
                 : "=r"(r[0]), "=r"(r[1]), "=r"(r[2]), "=r"(r[3]) : "r"(addr));
}
__device__ __forceinline__ void mma_h(float* d, const uint32_t* a,
                                      const uint32_t* b) {
    asm volatile(
        "mma.sync.aligned.m16n8k16.row.col.f32.f16.f16.f32 "
        "{%0,%1,%2,%3}, {%4,%5,%6,%7}, {%8,%9}, {%0,%1,%2,%3};"
        : "+f"(d[0]), "+f"(d[1]), "+f"(d[2]), "+f"(d[3])
        : "r"(a[0]), "r"(a[1]), "r"(a[2]), "r"(a[3]), "r"(b[0]), "r"(b[1]));
}
__device__ __forceinline__ float ex2(float x) {
    float y;
    asm("ex2.approx.ftz.f32 %0, %1;" : "=f"(y) : "f"(x));
    return y;
}
__device__ __forceinline__ void split2(float a, float b, uint32_t& hp, uint32_t& lp) {
    __half ha = __float2half_rn(a), hb = __float2half_rn(b);
    hp = (uint32_t)__half_as_ushort(ha) | ((uint32_t)__half_as_ushort(hb) << 16);
    __half la = __float2half_rn(a - __half2float(ha));
    __half lb = __float2half_rn(b - __half2float(hb));
    lp = (uint32_t)__half_as_ushort(la) | ((uint32_t)__half_as_ushort(lb) << 16);
}

// ============================================================================
// fp16 split-precision GEMM, 2-PASS: C = (Ah+Al)*Bh^T, fp32 accum.
// (Weight-lo term A*Bl dropped: ~2^-12 relative, randomized over K=2048.)
// BK=32, 2-stage cp.async, 128x128 CTA tile, 8 warps (4x2), warp 32x64.
// MODE 0: fp32 C out.  MODE 1: fused RoPE + hi/lo split + [h][s][d] scatter.
// ============================================================================
#define BK 32
#define ROWB 80
#define TILE_B (128 * ROWB)             // 10240
#define STAGE_B (3 * TILE_B)            // Ah, Al, Bh = 30720
#define GEMM_SMEM (2 * STAGE_B)         // 61440

template <int MODE>
__global__ __launch_bounds__(256, 2) void gemm_hs(
    const __half* __restrict__ Ah, const __half* __restrict__ Al,
    const __half* __restrict__ Bh,
    float* __restrict__ C, const float* __restrict__ cosb,
    const float* __restrict__ sinb, int N, int K) {
    extern __shared__ __align__(128) char dsm[];
    const uint32_t base = smem_u32(dsm);

    const int tid = threadIdx.x;
    const int wid = tid >> 5;
    const int lane = tid & 31;
    const int wm = wid >> 1;
    const int wn = wid & 1;
    const int bm = blockIdx.y * 128;
    const int bn = blockIdx.x * 128;
    const int nchunk = K / BK;

    float acc[2][8][4];
#pragma unroll
    for (int i = 0; i < 2; i++)
#pragma unroll
        for (int j = 0; j < 8; j++)
#pragma unroll
            for (int k = 0; k < 4; k++) acc[i][j][k] = 0.f;

    auto load_chunk = [&](int chunk, int stage) {
        const int k0 = chunk * BK;
        const uint32_t sb = base + stage * STAGE_B;
#pragma unroll
        for (int t = 0; t < 3; t++) {
            const __half* src = (t == 0) ? Ah : (t == 1) ? Al : Bh;
            const int rowbase = (t < 2) ? bm : bn;
            const uint32_t tb = sb + t * TILE_B;
#pragma unroll
            for (int i = 0; i < 2; i++) {
                int c = tid + i * 256;
                int r = c >> 2;
                int cc = c & 3;
                cp16(tb + r * ROWB + cc * 16,
                     src + (size_t)(rowbase + r) * K + k0 + cc * 8);
            }
        }
        CP_COMMIT();
    };

    const int a_row = lane & 15;
    const int a_kh  = lane >> 4;
    const int b_row = (lane & 7) + ((lane >> 4) << 3);
    const int b_kh  = (lane >> 3) & 1;

    auto compute = [&](int stage) {
        const uint32_t sb  = base + stage * STAGE_B;
        const uint32_t sAh = sb;
        const uint32_t sAl = sb + TILE_B;
        const uint32_t sBh = sb + 2 * TILE_B;
#pragma unroll
        for (int ks = 0; ks < 2; ks++) {
            const uint32_t ko = ks * 32 + a_kh * 16;
            uint32_t afh[2][4], afl[2][4];
#pragma unroll
            for (int ma = 0; ma < 2; ma++) {
                const uint32_t ro = (uint32_t)(wm * 32 + ma * 16 + a_row) * ROWB;
                ldmx4(afh[ma], sAh + ro + ko);
                ldmx4(afl[ma], sAl + ro + ko);
            }
            const uint32_t bko = ks * 32 + b_kh * 16;
#pragma unroll
            for (int nb = 0; nb < 4; nb++) {
                uint32_t bf[4];
                ldmx4(bf, sBh + (uint32_t)(wn * 64 + nb * 16 + b_row) * ROWB + bko);
#pragma unroll
                for (int ma = 0; ma < 2; ma++) {
                    mma_h(acc[ma][2 * nb],     afh[ma], bf);
                    mma_h(acc[ma][2 * nb + 1], afh[ma], bf + 2);
                    mma_h(acc[ma][2 * nb],     afl[ma], bf);
                    mma_h(acc[ma][2 * nb + 1], afl[ma], bf + 2);
                }
            }
        }
    };

    load_chunk(0, 0);
    for (int i = 0; i < nchunk; i++) {
        if (i + 1 < nchunk) {
            load_chunk(i + 1, (i + 1) & 1);
            asm volatile("cp.async.wait_group 1;" ::: "memory");
        } else {
            asm volatile("cp.async.wait_group 0;" ::: "memory");
        }
        __syncthreads();
        compute(i & 1);
        __syncthreads();
    }

    if (MODE == 0) {
#pragma unroll
        for (int ma = 0; ma < 2; ma++) {
            const int r0 = bm + wm * 32 + ma * 16 + (lane >> 2);
            const int cb = bn + wn * 64 + 2 * (lane & 3);
#pragma unroll
            for (int half = 0; half < 2; half++) {
                float* crow = C + (size_t)(r0 + half * 8) * N + cb;
#pragma unroll
                for (int na = 0; na < 8; na++)
                    *(float2*)(crow + na * 8) =
                        make_float2(acc[ma][na][half * 2], acc[ma][na][half * 2 + 1]);
            }
        }
    } else {
        // fused RoPE + hi/lo split + [h][s][d] scatter
        const int hh = (bn + wn * 64) >> 6;
#pragma unroll
        for (int ma = 0; ma < 2; ma++) {
#pragma unroll
            for (int half = 0; half < 2; half++) {
                const int s = bm + wm * 32 + ma * 16 + (lane >> 2) + half * 8;
                if (hh < NH + NKV) {
#pragma unroll
                    for (int na = 0; na < 4; na++) {
                        const int d = na * 8 + 2 * (lane & 3);
                        float2 cl = *(const float2*)(cosb + s * HD + d);
                        float2 sl = *(const float2*)(sinb + s * HD + d);
                        float2 ch = *(const float2*)(cosb + s * HD + d + 32);
                        float2 sh = *(const float2*)(sinb + s * HD + d + 32);
                        float v0 = acc[ma][na][half * 2];
                        float v1 = acc[ma][na][half * 2 + 1];
                        float w0 = acc[ma][na + 4][half * 2];
                        float w1 = acc[ma][na + 4][half * 2 + 1];
                        float r0 = v0 * cl.x - w0 * sl.x;
                        float r1 = v1 * cl.y - w1 * sl.y;
                        float u0 = w0 * ch.x + v0 * sh.x;
                        float u1 = w1 * ch.y + v1 * sh.y;
                        uint32_t hp, lp, hp2, lp2;
                        split2(r0, r1, hp, lp);
                        split2(u0, u1, hp2, lp2);
                        if (hh < NH) {
                            size_t a0 = ((size_t)(hh * S_LEN + s) << 6) + d;
                            *(uint32_t*)(g_qhh + a0) = hp;
                            *(uint32_t*)(g_qhl + a0) = lp;
                            *(uint32_t*)(g_qhh + a0 + 32) = hp2;
                            *(uint32_t*)(g_qhl + a0 + 32) = lp2;
                        } else {
                            size_t a0 = ((size_t)((hh - NH) * S_LEN + s) << 6) + d;
                            *(uint32_t*)(g_khh + a0) = hp;
                            *(uint32_t*)(g_khl + a0) = lp;
                            *(uint32_t*)(g_khh + a0 + 32) = hp2;
                            *(uint32_t*)(g_khl + a0 + 32) = lp2;
                        }
                    }
                } else {
#pragma unroll
                    for (int na = 0; na < 8; na++) {
                        const int d = na * 8 + 2 * (lane & 3);
                        uint32_t hp, lp;
                        split2(acc[ma][na][half * 2], acc[ma][na][half * 2 + 1],
                               hp, lp);
                        size_t a0 = ((size_t)((hh - NH - NKV) * S_LEN + s) << 6) + d;
                        *(uint32_t*)(g_vhh + a0) = hp;
                        *(uint32_t*)(g_vhl + a0) = lp;
                    }
                }
            }
        }
    }
}

// ============================================================================
// Input prep, ONE launch: x -> hi/lo split ; w_qkv, w_out -> plain fp16
// ============================================================================
#define N4_X  (S_LEN * HID / 4)
#define N4_WQ (QKV_OUT * HID / 4)
#define N4_WO (HID * HID / 4)
#define N4_ALL (N4_X + N4_WQ + N4_WO)

__global__ __launch_bounds__(256) void split_all(
    const float* __restrict__ x, const float* __restrict__ wq,
    const float* __restrict__ wo) {
    int i = blockIdx.x * 256 + threadIdx.x;
    if (i >= N4_ALL) return;
    int j = i;
    if (j < N4_X) {
        float4 v = ((const float4*)x)[j];
        uint32_t h0, l0, h1, l1;
        split2(v.x, v.y, h0, l0);
        split2(v.z, v.w, h1, l1);
        ((uint2*)g_xh)[j] = make_uint2(h0, h1);
        ((uint2*)g_xl)[j] = make_uint2(l0, l1);
        return;
    }
    const float* in;
    __half* hi;
    if ((j -= N4_X) < N4_WQ) { in = wq; hi = g_wqh; }
    else { j -= N4_WQ; in = wo; hi = g_woh; }
    float4 v = ((const float4*)in)[j];
    __half2 h0 = __floats2half2_rn(v.x, v.y);
    __half2 h1 = __floats2half2_rn(v.z, v.w);
    ((uint2*)hi)[j] = make_uint2(*(uint32_t*)&h0, *(uint32_t*)&h1);
}

// ============================================================================
// fp16 split-precision (3-pass) flash attention — round-14 champion verbatim.
// Q tile 64 rows, 128 threads, 2 CTAs/SM. grid (32 qb, 32 h).
// ============================================================================
#define AROWB 144
#define AQ_B   (64 * AROWB)              // 9216
#define AKV_B  (64 * AROWB)              // 9216
#define AST_B  (4 * AKV_B)               // Kh,Kl,Vh,Vl = 36864
#define ATTN_SMEM (2 * AQ_B + 2 * AST_B) // 92160

__global__ __launch_bounds__(128, 2) void flash_attn_s() {
    extern __shared__ __align__(128) char dsm[];
    const uint32_t base = smem_u32(dsm);
    const uint32_t sQh = base;
    const uint32_t sQl = base + AQ_B;
    const uint32_t ringb = base + 2 * AQ_B;

    const int qb = 31 - (int)blockIdx.x;     // heavy CTAs first
    const int h  = blockIdx.y;
    const __half* Qhg = g_qhh + (size_t)(h * S_LEN + qb * 64) * HD;
    const __half* Qlg = g_qhl + (size_t)(h * S_LEN + qb * 64) * HD;
    const size_t kvo = (size_t)((h >> 2) * S_LEN) * HD;
    const __half* Khg = g_khh + kvo;
    const __half* Klg = g_khl + kvo;
    const __half* Vhg = g_vhh + kvo;
    const __half* Vlg = g_vhl + kvo;

    const int tid = threadIdx.x;
    const int wq = tid >> 5;
    const int lane = tid & 31;

#pragma unroll
    for (int i = 0; i < 4; i++) {
        int c = tid + i * 128;
        int r = c >> 3, c8 = c & 7;
        cp16(sQh + r * AROWB + c8 * 16, Qhg + r * HD + c8 * 8);
        cp16(sQl + r * AROWB + c8 * 16, Qlg + r * HD + c8 * 8);
    }
    CP_COMMIT();

    auto load_kv = [&](int kb, int st) {
        const uint32_t sb = ringb + st * AST_B;
#pragma unroll
        for (int i = 0; i < 4; i++) {
            int c = tid + i * 128;
            int r = c >> 3, c8 = c & 7;
            const size_t go = (size_t)(kb * 64 + r) * HD + c8 * 8;
            const uint32_t so = r * AROWB + c8 * 16;
            cp16(sb + so,             Khg + go);
            cp16(sb + AKV_B + so,     Klg + go);
            cp16(sb + 2 * AKV_B + so, Vhg + go);
            cp16(sb + 3 * AKV_B + so, Vlg + go);
        }
        CP_COMMIT();
    };

    const int a_row = lane & 15;
    const int a_kh  = lane >> 4;
    const int b_row = (lane & 7) + ((lane >> 4) << 3);
    const int b_kh  = (lane >> 3) & 1;
    const int v_row = (lane & 7) + ((lane >> 3) & 1) * 8;
    const int v_nh  = (lane >> 4) * 8;

    uint32_t qah[4][4], qal[4][4];
    float oacc[8][4];
    float m_lo = -1e30f, m_hi = -1e30f, l_lo = 0.f, l_hi = 0.f;
#pragma unroll
    for (int a = 0; a < 8; a++)
#pragma unroll
        for (int r = 0; r < 4; r++) oacc[a][r] = 0.f;

    const float sscale = 0.125f * 1.44269504f;
    const int row_lo = qb * 64 + wq * 16 + (lane >> 2);
    const int nkb = qb + 1;

    load_kv(0, 0);

    for (int i = 0; i < nkb; i++) {
        const int st = i & 1;
        if (i + 1 < nkb) {
            load_kv(i + 1, st ^ 1);
            asm volatile("cp.async.wait_group 1;" ::: "memory");
        } else {
            asm volatile("cp.async.wait_group 0;" ::: "memory");
        }
        __syncthreads();

        if (i == 0) {
#pragma unroll
            for (int ka = 0; ka < 4; ka++) {
                const uint32_t qo = (uint32_t)(wq * 16 + a_row) * AROWB +
                                    ka * 32 + a_kh * 16;
                ldmx4(qah[ka], sQh + qo);
                ldmx4(qal[ka], sQl + qo);
            }
        }

        const uint32_t sKh = ringb + st * AST_B;
        const uint32_t sKl = sKh + AKV_B;
        const uint32_t sVh = sKh + 2 * AKV_B;
        const uint32_t sVl = sKh + 3 * AKV_B;

        // ---- S = Q K^T  (3-pass) ----
        float sacc[8][4];
#pragma unroll
        for (int a = 0; a < 8; a++)
#pragma unroll
            for (int r = 0; r < 4; r++) sacc[a][r] = 0.f;
#pragma unroll
        for (int ka = 0; ka < 4; ka++) {
            const uint32_t bko = ka * 32 + b_kh * 16;
#pragma unroll
            for (int nb = 0; nb < 4; nb++) {
                const uint32_t ro = (uint32_t)(nb * 16 + b_row) * AROWB + bko;
                uint32_t bh[4], bl[4];
                ldmx4(bh, sKh + ro);
                ldmx4(bl, sKl + ro);
                mma_h(sacc[2 * nb],     qah[ka], bh);
                mma_h(sacc[2 * nb + 1], qah[ka], bh + 2);
                mma_h(sacc[2 * nb],     qah[ka], bl);
                mma_h(sacc[2 * nb + 1], qah[ka], bl + 2);
                mma_h(sacc[2 * nb],     qal[ka], bh);
                mma_h(sacc[2 * nb + 1], qal[ka], bh + 2);
            }
        }

        // ---- scale + causal mask ----
        const bool need_mask = (i * 64 + 63) > (qb * 64 + wq * 16);
        if (need_mask) {
#pragma unroll
            for (int a = 0; a < 8; a++) {
                const int colb = i * 64 + a * 8 + 2 * (lane & 3);
#pragma unroll
                for (int r = 0; r < 4; r++) {
                    const int col = colb + (r & 1);
                    const int row = row_lo + (r >> 1) * 8;
                    sacc[a][r] = (col > row) ? -1e30f : sacc[a][r] * sscale;
                }
            }
        } else {
#pragma unroll
            for (int a = 0; a < 8; a++)
#pragma unroll
                for (int r = 0; r < 4; r++) sacc[a][r] *= sscale;
        }

        // ---- online softmax ----
        float tmlo = -1e30f, tmhi = -1e30f;
#pragma unroll
        for (int a = 0; a < 8; a++) {
            tmlo = fmaxf(tmlo, fmaxf(sacc[a][0], sacc[a][1]));
            tmhi = fmaxf(tmhi, fmaxf(sacc[a][2], sacc[a][3]));
        }
#pragma unroll
        for (int off = 1; off <= 2; off <<= 1) {
            tmlo = fmaxf(tmlo, __shfl_xor_sync(0xffffffffu, tmlo, off));
            tmhi = fmaxf(tmhi, __shfl_xor_sync(0xffffffffu, tmhi, off));
        }
        const float mn_lo = fmaxf(m_lo, tmlo);
        const float mn_hi = fmaxf(m_hi, tmhi);
        const float corr_lo = ex2(m_lo - mn_lo);
        const float corr_hi = ex2(m_hi - mn_hi);
        m_lo = mn_lo; m_hi = mn_hi;

        float rs_lo = 0.f, rs_hi = 0.f;
#pragma unroll
        for (int a = 0; a < 8; a++) {
            sacc[a][0] = ex2(sacc[a][0] - mn_lo);
            sacc[a][1] = ex2(sacc[a][1] - mn_lo);
            sacc[a][2] = ex2(sacc[a][2] - mn_hi);
            sacc[a][3] = ex2(sacc[a][3] - mn_hi);
            rs_lo += sacc[a][0] + sacc[a][1];
            rs_hi += sacc[a][2] + sacc[a][3];
        }
#pragma unroll
        for (int off = 1; off <= 2; off <<= 1) {
            rs_lo += __shfl_xor_sync(0xffffffffu, rs_lo, off);
            rs_hi += __shfl_xor_sync(0xffffffffu, rs_hi, off);
        }
        l_lo = l_lo * corr_lo + rs_lo;
        l_hi = l_hi * corr_hi + rs_hi;
#pragma unroll
        for (int a = 0; a < 8; a++) {
            oacc[a][0] *= corr_lo; oacc[a][1] *= corr_lo;
            oacc[a][2] *= corr_hi; oacc[a][3] *= corr_hi;
        }

        // ---- O += P V  (3-pass) ----
#pragma unroll
        for (int ka = 0; ka < 4; ka++) {
            uint32_t pah[4], pal[4];
            split2(sacc[2 * ka][0],     sacc[2 * ka][1],     pah[0], pal[0]);
            split2(sacc[2 * ka][2],     sacc[2 * ka][3],     pah[1], pal[1]);
            split2(sacc[2 * ka + 1][0], sacc[2 * ka + 1][1], pah[2], pal[2]);
            split2(sacc[2 * ka + 1][2], sacc[2 * ka + 1][3], pah[3], pal[3]);
#pragma unroll
            for (int nd = 0; nd < 4; nd++) {
                const uint32_t vo = (uint32_t)(ka * 16 + v_row) * AROWB +
                                    (uint32_t)(nd * 16 + v_nh) * 2;
                uint32_t vh[4], vl[4];
                ldmx4t(vh, sVh + vo);
                ldmx4t(vl, sVl + vo);
                mma_h(oacc[2 * nd],     pah, vh);
                mma_h(oacc[2 * nd + 1], pah, vh + 2);
                mma_h(oacc[2 * nd],     pah, vl);
                mma_h(oacc[2 * nd + 1], pah, vl + 2);
                mma_h(oacc[2 * nd],     pal, vh);
                mma_h(oacc[2 * nd + 1], pal, vh + 2);
            }
        }
        __syncthreads();
    }

    // ---- normalize + write split fp16 to g_ahh/g_ahl [s][h*64+d] ----
    const float inv_lo = 1.f / l_lo;
    const float inv_hi = 1.f / l_hi;
    const int srow_lo = qb * 64 + wq * 16 + (lane >> 2);
#pragma unroll
    for (int a = 0; a < 8; a++) {
        const int col = h * 64 + a * 8 + 2 * (lane & 3);
        uint32_t hp, lp;
        split2(oacc[a][0] * inv_lo, oacc[a][1] * inv_lo, hp, lp);
        *(uint32_t*)(g_ahh + (size_t)srow_lo * HID + col) = hp;
        *(uint32_t*)(g_ahl + (size_t)srow_lo * HID + col) = lp;
        split2(oacc[a][2] * inv_hi, oacc[a][3] * inv_hi, hp, lp);
        *(uint32_t*)(g_ahh + (size_t)(srow_lo + 8) * HID + col) = hp;
        *(uint32_t*)(g_ahl + (size_t)(srow_lo + 8) * HID + col) = lp;
    }
}

// =====================================================================
extern "C" void kernel_launch(void* const* d_in, const int* in_sizes, int n_in,
                              void* d_out, int out_size) {
    const float* x     = (const float*)d_in[0];
    const float* cosb  = (const float*)d_in[1];
    const float* sinb  = (const float*)d_in[2];
    const float* w_qkv = (const float*)d_in[3];
    const float* w_out = (const float*)d_in[4];
    float* out = (float*)d_out;

    __half *xh, *xl, *wqh, *woh, *ahh, *ahl;
    cudaGetSymbolAddress((void**)&xh, g_xh);
    cudaGetSymbolAddress((void**)&xl, g_xl);
    cudaGetSymbolAddress((void**)&wqh, g_wqh);
    cudaGetSymbolAddress((void**)&woh, g_woh);
    cudaGetSymbolAddress((void**)&ahh, g_ahh);
    cudaGetSymbolAddress((void**)&ahl, g_ahl);

    cudaFuncSetAttribute(gemm_hs<0>, cudaFuncAttributeMaxDynamicSharedMemorySize,
                         GEMM_SMEM);
    cudaFuncSetAttribute(gemm_hs<1>, cudaFuncAttributeMaxDynamicSharedMemorySize,
                         GEMM_SMEM);
    cudaFuncSetAttribute(flash_attn_s, cudaFuncAttributeMaxDynamicSharedMemorySize,
                         ATTN_SMEM);

    // 0) input prep: x hi/lo split, weights plain fp16 (single launch)
    split_all<<<(N4_ALL + 255) / 256, 256>>>(x, w_qkv, w_out);

    // 1) QKV projection (2-pass) + fused RoPE/split/transpose
    gemm_hs<1><<<dim3(QKV_OUT / 128, S_LEN / 128), 256, GEMM_SMEM>>>(
        xh, xl, wqh, nullptr, cosb, sinb, QKV_OUT, HID);
    // 2) 3-pass fp16 split flash attention (unchanged)
    flash_attn_s<<<dim3(32, NH), 128, ATTN_SMEM>>>();
    // 3) out-projection (2-pass), fp32 out
    gemm_hs<0><<<dim3(HID / 128, S_LEN / 128), 256, GEMM_SMEM>>>(
        ahh, ahl, woh, out, nullptr, nullptr, HID, NH * HD);
}

// round 16
// speedup vs baseline: 1.5631x; 1.0654x over previous
#include <cuda_runtime.h>
#include <cuda_fp16.h>
#include <cstdint>

#define S_LEN 2048
#define HID 2048
#define NH 32
#define NKV 8
#define HD 64
#define QKV_OUT 3072   // (32 + 2*8) * 64

// ---------------- scratch (static device globals; no allocation) ----------------
__device__ __align__(16) __half g_xh[S_LEN * HID],  g_xl[S_LEN * HID];
__device__ __align__(16) __half g_wqh[QKV_OUT * HID];
__device__ __align__(16) __half g_woh[HID * HID];
__device__ __align__(16) __half g_qhh[NH * S_LEN * HD],  g_qhl[NH * S_LEN * HD];
__device__ __align__(16) __half g_khh[NKV * S_LEN * HD];            // K plain fp16
__device__ __align__(16) __half g_vhh[NKV * S_LEN * HD], g_vhl[NKV * S_LEN * HD];
__device__ __align__(16) __half g_ahh[S_LEN * HID], g_ahl[S_LEN * HID];

// ============================ helpers ============================
__device__ __forceinline__ uint32_t smem_u32(const void* p) {
    uint32_t a;
    asm("{ .reg .u64 t; cvta.to.shared.u64 t, %1; cvt.u32.u64 %0, t; }"
        : "=r"(a) : "l"(p));
    return a;
}
__device__ __forceinline__ void cp16(uint32_t s, const void* g) {
    asm volatile("cp.async.cg.shared.global [%0], [%1], 16;" :: "r"(s), "l"(g));
}
#define CP_COMMIT() asm volatile("cp.async.commit_group;" ::: "memory")

__device__ __forceinline__ void ldmx4(uint32_t* r, uint32_t addr) {
    asm volatile("ldmatrix.sync.aligned.m8n8.x4.shared.b16 {%0,%1,%2,%3}, [%4];"
                 : "=r"(r[0]), "=r"(r[1]), "=r"(r[2]), "=r"(r[3]) : "r"(addr));
}
__device__ __forceinline__ void ldmx4t(uint32_t* r, uint32_t addr) {
    asm volatile("ldmatrix.sync.aligned.m8n8.x4.trans.shared.b16 {%0,%1,%2,%3}, [%4];"
                 : "=r"(r[0]), "=r"(r[1]), "=r"(r[2]), "=r"(r[3]) : "r"(addr));
}
__device__ __forceinline__ void mma_h(float* d, const uint32_t* a,
                                      const uint32_t* b) {
    asm volatile(
        "mma.sync.aligned.m16n8k16.row.col.f32.f16.f16.f32 "
        "{%0,%1,%2,%3}, {%4,%5,%6,%7}, {%8,%9}, {%0,%1,%2,%3};"
        : "+f"(d[0]), "+f"(d[1]), "+f"(d[2]), "+f"(d[3])
        : "r"(a[0]), "r"(a[1]), "r"(a[2]), "r"(a[3]), "r"(b[0]), "r"(b[1]));
}
__device__ __forceinline__ float ex2(float x) {
    float y;
    asm("ex2.approx.ftz.f32 %0, %1;" : "=f"(y) : "f"(x));
    return y;
}
__device__ __forceinline__ void split2(float a, float b, uint32_t& hp, uint32_t& lp) {
    __half ha = __float2half_rn(a), hb = __float2half_rn(b);
    hp = (uint32_t)__half_as_ushort(ha) | ((uint32_t)__half_as_ushort(hb) << 16);
    __half la = __float2half_rn(a - __half2float(ha));
    __half lb = __float2half_rn(b - __half2float(hb));
    lp = (uint32_t)__half_as_ushort(la) | ((uint32_t)__half_as_ushort(lb) << 16);
}
__device__ __forceinline__ uint32_t packh2(float a, float b) {
    __half2 h = __floats2half2_rn(a, b);
    return *(uint32_t*)&h;
}

// ============================================================================
// fp16 split-precision GEMM, 2-PASS: C = (Ah+Al)*Bh^T, fp32 accum.
// Round-15 champion verbatim (incl. fused RoPE epilogue; K now plain fp16).
// ============================================================================
#define BK 32
#define ROWB 80
#define TILE_B (128 * ROWB)             // 10240
#define STAGE_B (3 * TILE_B)            // Ah, Al, Bh = 30720
#define GEMM_SMEM (2 * STAGE_B)         // 61440

template <int MODE>
__global__ __launch_bounds__(256, 2) void gemm_hs(
    const __half* __restrict__ Ah, const __half* __restrict__ Al,
    const __half* __restrict__ Bh,
    float* __restrict__ C, const float* __restrict__ cosb,
    const float* __restrict__ sinb, int N, int K) {
    extern __shared__ __align__(128) char dsm[];
    const uint32_t base = smem_u32(dsm);

    const int tid = threadIdx.x;
    const int wid = tid >> 5;
    const int lane = tid & 31;
    const int wm = wid >> 1;
    const int wn = wid & 1;
    const int bm = blockIdx.y * 128;
    const int bn = blockIdx.x * 128;
    const int nchunk = K / BK;

    float acc[2][8][4];
#pragma unroll
    for (int i = 0; i < 2; i++)
#pragma unroll
        for (int j = 0; j < 8; j++)
#pragma unroll
            for (int k = 0; k < 4; k++) acc[i][j][k] = 0.f;

    auto load_chunk = [&](int chunk, int stage) {
        const int k0 = chunk * BK;
        const uint32_t sb = base + stage * STAGE_B;
#pragma unroll
        for (int t = 0; t < 3; t++) {
            const __half* src = (t == 0) ? Ah : (t == 1) ? Al : Bh;
            const int rowbase = (t < 2) ? bm : bn;
            const uint32_t tb = sb + t * TILE_B;
#pragma unroll
            for (int i = 0; i < 2; i++) {
                int c = tid + i * 256;
                int r = c >> 2;
                int cc = c & 3;
                cp16(tb + r * ROWB + cc * 16,
                     src + (size_t)(rowbase + r) * K + k0 + cc * 8);
            }
        }
        CP_COMMIT();
    };

    const int a_row = lane & 15;
    const int a_kh  = lane >> 4;
    const int b_row = (lane & 7) + ((lane >> 4) << 3);
    const int b_kh  = (lane >> 3) & 1;

    auto compute = [&](int stage) {
        const uint32_t sb  = base + stage * STAGE_B;
        const uint32_t sAh = sb;
        const uint32_t sAl = sb + TILE_B;
        const uint32_t sBh = sb + 2 * TILE_B;
#pragma unroll
        for (int ks = 0; ks < 2; ks++) {
            const uint32_t ko = ks * 32 + a_kh * 16;
            uint32_t afh[2][4], afl[2][4];
#pragma unroll
            for (int ma = 0; ma < 2; ma++) {
                const uint32_t ro = (uint32_t)(wm * 32 + ma * 16 + a_row) * ROWB;
                ldmx4(afh[ma], sAh + ro + ko);
                ldmx4(afl[ma], sAl + ro + ko);
            }
            const uint32_t bko = ks * 32 + b_kh * 16;
#pragma unroll
            for (int nb = 0; nb < 4; nb++) {
                uint32_t bf[4];
                ldmx4(bf, sBh + (uint32_t)(wn * 64 + nb * 16 + b_row) * ROWB + bko);
#pragma unroll
                for (int ma = 0; ma < 2; ma++) {
                    mma_h(acc[ma][2 * nb],     afh[ma], bf);
                    mma_h(acc[ma][2 * nb + 1], afh[ma], bf + 2);
                    mma_h(acc[ma][2 * nb],     afl[ma], bf);
                    mma_h(acc[ma][2 * nb + 1], afl[ma], bf + 2);
                }
            }
        }
    };

    load_chunk(0, 0);
    for (int i = 0; i < nchunk; i++) {
        if (i + 1 < nchunk) {
            load_chunk(i + 1, (i + 1) & 1);
            asm volatile("cp.async.wait_group 1;" ::: "memory");
        } else {
            asm volatile("cp.async.wait_group 0;" ::: "memory");
        }
        __syncthreads();
        compute(i & 1);
        __syncthreads();
    }

    if (MODE == 0) {
#pragma unroll
        for (int ma = 0; ma < 2; ma++) {
            const int r0 = bm + wm * 32 + ma * 16 + (lane >> 2);
            const int cb = bn + wn * 64 + 2 * (lane & 3);
#pragma unroll
            for (int half = 0; half < 2; half++) {
                float* crow = C + (size_t)(r0 + half * 8) * N + cb;
#pragma unroll
                for (int na = 0; na < 8; na++)
                    *(float2*)(crow + na * 8) =
                        make_float2(acc[ma][na][half * 2], acc[ma][na][half * 2 + 1]);
            }
        }
    } else {
        // fused RoPE + split/convert + [h][s][d] scatter
        const int hh = (bn + wn * 64) >> 6;
#pragma unroll
        for (int ma = 0; ma < 2; ma++) {
#pragma unroll
            for (int half = 0; half < 2; half++) {
                const int s = bm + wm * 32 + ma * 16 + (lane >> 2) + half * 8;
                if (hh < NH + NKV) {
#pragma unroll
                    for (int na = 0; na < 4; na++) {
                        const int d = na * 8 + 2 * (lane & 3);
                        float2 cl = *(const float2*)(cosb + s * HD + d);
                        float2 sl = *(const float2*)(sinb + s * HD + d);
                        float2 ch = *(const float2*)(cosb + s * HD + d + 32);
                        float2 sh = *(const float2*)(sinb + s * HD + d + 32);
                        float v0 = acc[ma][na][half * 2];
                        float v1 = acc[ma][na][half * 2 + 1];
                        float w0 = acc[ma][na + 4][half * 2];
                        float w1 = acc[ma][na + 4][half * 2 + 1];
                        float r0 = v0 * cl.x - w0 * sl.x;
                        float r1 = v1 * cl.y - w1 * sl.y;
                        float u0 = w0 * ch.x + v0 * sh.x;
                        float u1 = w1 * ch.y + v1 * sh.y;
                        if (hh < NH) {
                            uint32_t hp, lp, hp2, lp2;
                            split2(r0, r1, hp, lp);
                            split2(u0, u1, hp2, lp2);
                            size_t a0 = ((size_t)(hh * S_LEN + s) << 6) + d;
                            *(uint32_t*)(g_qhh + a0) = hp;
                            *(uint32_t*)(g_qhl + a0) = lp;
                            *(uint32_t*)(g_qhh + a0 + 32) = hp2;
                            *(uint32_t*)(g_qhl + a0 + 32) = lp2;
                        } else {
                            // K: plain fp16 (lo term dropped in attention S)
                            size_t a0 = ((size_t)((hh - NH) * S_LEN + s) << 6) + d;
                            *(uint32_t*)(g_khh + a0) = packh2(r0, r1);
                            *(uint32_t*)(g_khh + a0 + 32) = packh2(u0, u1);
                        }
                    }
                } else {
#pragma unroll
                    for (int na = 0; na < 8; na++) {
                        const int d = na * 8 + 2 * (lane & 3);
                        uint32_t hp, lp;
                        split2(acc[ma][na][half * 2], acc[ma][na][half * 2 + 1],
                               hp, lp);
                        size_t a0 = ((size_t)((hh - NH - NKV) * S_LEN + s) << 6) + d;
                        *(uint32_t*)(g_vhh + a0) = hp;
                        *(uint32_t*)(g_vhl + a0) = lp;
                    }
                }
            }
        }
    }
}

// ============================================================================
// Input prep, ONE launch: x -> hi/lo split ; w_qkv, w_out -> plain fp16
// ============================================================================
#define N4_X  (S_LEN * HID / 4)
#define N4_WQ (QKV_OUT * HID / 4)
#define N4_WO (HID * HID / 4)
#define N4_ALL (N4_X + N4_WQ + N4_WO)

__global__ __launch_bounds__(256) void split_all(
    const float* __restrict__ x, const float* __restrict__ wq,
    const float* __restrict__ wo) {
    int i = blockIdx.x * 256 + threadIdx.x;
    if (i >= N4_ALL) return;
    int j = i;
    if (j < N4_X) {
        float4 v = ((const float4*)x)[j];
        uint32_t h0, l0, h1, l1;
        split2(v.x, v.y, h0, l0);
        split2(v.z, v.w, h1, l1);
        ((uint2*)g_xh)[j] = make_uint2(h0, h1);
        ((uint2*)g_xl)[j] = make_uint2(l0, l1);
        return;
    }
    const float* in;
    __half* hi;
    if ((j -= N4_X) < N4_WQ) { in = wq; hi = g_wqh; }
    else { j -= N4_WQ; in = wo; hi = g_woh; }
    float4 v = ((const float4*)in)[j];
    __half2 h0 = __floats2half2_rn(v.x, v.y);
    __half2 h1 = __floats2half2_rn(v.z, v.w);
    ((uint2*)hi)[j] = make_uint2(*(uint32_t*)&h0, *(uint32_t*)&h1);
}

// ============================================================================
// fp16 split flash attention: S 2-pass ((Qh+Ql)*K, K plain fp16),
// PV 3-pass (P split x (Vh+Vl)). Q tile 64 rows, 128 threads.
// KV ring = 3 tiles/stage (K, Vh, Vl); smem 73728 -> >=2 CTAs/SM.
// grid (32 qb, 32 h).
// ============================================================================
#define AROWB 144
#define AQ_B   (64 * AROWB)              // 9216
#define AKV_B  (64 * AROWB)              // 9216
#define AST_B  (3 * AKV_B)               // K, Vh, Vl = 27648
#define ATTN_SMEM (2 * AQ_B + 2 * AST_B) // 73728

__global__ __launch_bounds__(128, 2) void flash_attn_s() {
    extern __shared__ __align__(128) char dsm[];
    const uint32_t base = smem_u32(dsm);
    const uint32_t sQh = base;
    const uint32_t sQl = base + AQ_B;
    const uint32_t ringb = base + 2 * AQ_B;

    const int qb = 31 - (int)blockIdx.x;     // heavy CTAs first
    const int h  = blockIdx.y;
    const __half* Qhg = g_qhh + (size_t)(h * S_LEN + qb * 64) * HD;
    const __half* Qlg = g_qhl + (size_t)(h * S_LEN + qb * 64) * HD;
    const size_t kvo = (size_t)((h >> 2) * S_LEN) * HD;
    const __half* Kg  = g_khh + kvo;
    const __half* Vhg = g_vhh + kvo;
    const __half* Vlg = g_vhl + kvo;

    const int tid = threadIdx.x;
    const int wq = tid >> 5;
    const int lane = tid & 31;

#pragma unroll
    for (int i = 0; i < 4; i++) {
        int c = tid + i * 128;
        int r = c >> 3, c8 = c & 7;
        cp16(sQh + r * AROWB + c8 * 16, Qhg + r * HD + c8 * 8);
        cp16(sQl + r * AROWB + c8 * 16, Qlg + r * HD + c8 * 8);
    }
    CP_COMMIT();

    auto load_kv = [&](int kb, int st) {
        const uint32_t sb = ringb + st * AST_B;
#pragma unroll
        for (int i = 0; i < 4; i++) {
            int c = tid + i * 128;
            int r = c >> 3, c8 = c & 7;
            const size_t go = (size_t)(kb * 64 + r) * HD + c8 * 8;
            const uint32_t so = r * AROWB + c8 * 16;
            cp16(sb + so,             Kg + go);
            cp16(sb + AKV_B + so,     Vhg + go);
            cp16(sb + 2 * AKV_B + so, Vlg + go);
        }
        CP_COMMIT();
    };

    const int a_row = lane & 15;
    const int a_kh  = lane >> 4;
    const int b_row = (lane & 7) + ((lane >> 4) << 3);
    const int b_kh  = (lane >> 3) & 1;
    const int v_row = (lane & 7) + ((lane >> 3) & 1) * 8;
    const int v_nh  = (lane >> 4) * 8;

    uint32_t qah[4][4], qal[4][4];
    float oacc[8][4];
    float m_lo = -1e30f, m_hi = -1e30f, l_lo = 0.f, l_hi = 0.f;
#pragma unroll
    for (int a = 0; a < 8; a++)
#pragma unroll
        for (int r = 0; r < 4; r++) oacc[a][r] = 0.f;

    const float sscale = 0.125f * 1.44269504f;
    const int row_lo = qb * 64 + wq * 16 + (lane >> 2);
    const int nkb = qb + 1;

    load_kv(0, 0);

    for (int i = 0; i < nkb; i++) {
        const int st = i & 1;
        if (i + 1 < nkb) {
            load_kv(i + 1, st ^ 1);
            asm volatile("cp.async.wait_group 1;" ::: "memory");
        } else {
            asm volatile("cp.async.wait_group 0;" ::: "memory");
        }
        __syncthreads();

        if (i == 0) {
#pragma unroll
            for (int ka = 0; ka < 4; ka++) {
                const uint32_t qo = (uint32_t)(wq * 16 + a_row) * AROWB +
                                    ka * 32 + a_kh * 16;
                ldmx4(qah[ka], sQh + qo);
                ldmx4(qal[ka], sQl + qo);
            }
        }

        const uint32_t sK  = ringb + st * AST_B;
        const uint32_t sVh = sK + AKV_B;
        const uint32_t sVl = sK + 2 * AKV_B;

        // ---- S = Q K^T  (2-pass: Qh*K + Ql*K) ----
        float sacc[8][4];
#pragma unroll
        for (int a = 0; a < 8; a++)
#pragma unroll
            for (int r = 0; r < 4; r++) sacc[a][r] = 0.f;
#pragma unroll
        for (int ka = 0; ka < 4; ka++) {
            const uint32_t bko = ka * 32 + b_kh * 16;
#pragma unroll
            for (int nb = 0; nb < 4; nb++) {
                const uint32_t ro = (uint32_t)(nb * 16 + b_row) * AROWB + bko;
                uint32_t bh[4];
                ldmx4(bh, sK + ro);
                mma_h(sacc[2 * nb],     qah[ka], bh);
                mma_h(sacc[2 * nb + 1], qah[ka], bh + 2);
                mma_h(sacc[2 * nb],     qal[ka], bh);
                mma_h(sacc[2 * nb + 1], qal[ka], bh + 2);
            }
        }

        // ---- scale + causal mask ----
        const bool need_mask = (i * 64 + 63) > (qb * 64 + wq * 16);
        if (need_mask) {
#pragma unroll
            for (int a = 0; a < 8; a++) {
                const int colb = i * 64 + a * 8 + 2 * (lane & 3);
#pragma unroll
                for (int r = 0; r < 4; r++) {
                    const int col = colb + (r & 1);
                    const int row = row_lo + (r >> 1) * 8;
                    sacc[a][r] = (col > row) ? -1e30f : sacc[a][r] * sscale;
                }
            }
        } else {
#pragma unroll
            for (int a = 0; a < 8; a++)
#pragma unroll
                for (int r = 0; r < 4; r++) sacc[a][r] *= sscale;
        }

        // ---- online softmax ----
        float tmlo = -1e30f, tmhi = -1e30f;
#pragma unroll
        for (int a = 0; a < 8; a++) {
            tmlo = fmaxf(tmlo, fmaxf(sacc[a][0], sacc[a][1]));
            tmhi = fmaxf(tmhi, fmaxf(sacc[a][2], sacc[a][3]));
        }
#pragma unroll
        for (int off = 1; off <= 2; off <<= 1) {
            tmlo = fmaxf(tmlo, __shfl_xor_sync(0xffffffffu, tmlo, off));
            tmhi = fmaxf(tmhi, __shfl_xor_sync(0xffffffffu, tmhi, off));
        }
        const float mn_lo = fmaxf(m_lo, tmlo);
        const float mn_hi = fmaxf(m_hi, tmhi);
        const float corr_lo = ex2(m_lo - mn_lo);
        const float corr_hi = ex2(m_hi - mn_hi);
        m_lo = mn_lo; m_hi = mn_hi;

        float rs_lo = 0.f, rs_hi = 0.f;
#pragma unroll
        for (int a = 0; a < 8; a++) {
            sacc[a][0] = ex2(sacc[a][0] - mn_lo);
            sacc[a][1] = ex2(sacc[a][1] - mn_lo);
            sacc[a][2] = ex2(sacc[a][2] - mn_hi);
            sacc[a][3] = ex2(sacc[a][3] - mn_hi);
            rs_lo += sacc[a][0] + sacc[a][1];
            rs_hi += sacc[a][2] + sacc[a][3];
        }
#pragma unroll
        for (int off = 1; off <= 2; off <<= 1) {
            rs_lo += __shfl_xor_sync(0xffffffffu, rs_lo, off);
            rs_hi += __shfl_xor_sync(0xffffffffu, rs_hi, off);
        }
        l_lo = l_lo * corr_lo + rs_lo;
        l_hi = l_hi * corr_hi + rs_hi;
#pragma unroll
        for (int a = 0; a < 8; a++) {
            oacc[a][0] *= corr_lo; oacc[a][1] *= corr_lo;
            oacc[a][2] *= corr_hi; oacc[a][3] *= corr_hi;
        }

        // ---- O += P V  (3-pass: PhVh + PhVl + PlVh) ----
#pragma unroll
        for (int ka = 0; ka < 4; ka++) {
            uint32_t pah[4], pal[4];
            split2(sacc[2 * ka][0],     sacc[2 * ka][1],     pah[0], pal[0]);
            split2(sacc[2 * ka][2],     sacc[2 * ka][3],     pah[1], pal[1]);
            split2(sacc[2 * ka + 1][0], sacc[2 * ka + 1][1], pah[2], pal[2]);
            split2(sacc[2 * ka + 1][2], sacc[2 * ka + 1][3], pah[3], pal[3]);
#pragma unroll
            for (int nd = 0; nd < 4; nd++) {
                const uint32_t vo = (uint32_t)(ka * 16 + v_row) * AROWB +
                                    (uint32_t)(nd * 16 + v_nh) * 2;
                uint32_t vh[4], vl[4];
                ldmx4t(vh, sVh + vo);
                ldmx4t(vl, sVl + vo);
                mma_h(oacc[2 * nd],     pah, vh);
                mma_h(oacc[2 * nd + 1], pah, vh + 2);
                mma_h(oacc[2 * nd],     pah, vl);
                mma_h(oacc[2 * nd + 1], pah, vl + 2);
                mma_h(oacc[2 * nd],     pal, vh);
                mma_h(oacc[2 * nd + 1], pal, vh + 2);
            }
        }
        __syncthreads();
    }

    // ---- normalize + write split fp16 to g_ahh/g_ahl [s][h*64+d] ----
    const float inv_lo = 1.f / l_lo;
    const float inv_hi = 1.f / l_hi;
    const int srow_lo = qb * 64 + wq * 16 + (lane >> 2);
#pragma unroll
    for (int a = 0; a < 8; a++) {
        const int col = h * 64 + a * 8 + 2 * (lane & 3);
        uint32_t hp, lp;
        split2(oacc[a][0] * inv_lo, oacc[a][1] * inv_lo, hp, lp);
        *(uint32_t*)(g_ahh + (size_t)srow_lo * HID + col) = hp;
        *(uint32_t*)(g_ahl + (size_t)srow_lo * HID + col) = lp;
        split2(oacc[a][2] * inv_hi, oacc[a][3] * inv_hi, hp, lp);
        *(uint32_t*)(g_ahh + (size_t)(srow_lo + 8) * HID + col) = hp;
        *(uint32_t*)(g_ahl + (size_t)(srow_lo + 8) * HID + col) = lp;
    }
}

// =====================================================================
extern "C" void kernel_launch(void* const* d_in, const int* in_sizes, int n_in,
                              void* d_out, int out_size) {
    const float* x     = (const float*)d_in[0];
    const float* cosb  = (const float*)d_in[1];
    const float* sinb  = (const float*)d_in[2];
    const float* w_qkv = (const float*)d_in[3];
    const float* w_out = (const float*)d_in[4];
    float* out = (float*)d_out;

    __half *xh, *xl, *wqh, *woh, *ahh, *ahl;
    cudaGetSymbolAddress((void**)&xh, g_xh);
    cudaGetSymbolAddress((void**)&xl, g_xl);
    cudaGetSymbolAddress((void**)&wqh, g_wqh);
    cudaGetSymbolAddress((void**)&woh, g_woh);
    cudaGetSymbolAddress((void**)&ahh, g_ahh);
    cudaGetSymbolAddress((void**)&ahl, g_ahl);

    cudaFuncSetAttribute(gemm_hs<0>, cudaFuncAttributeMaxDynamicSharedMemorySize,
                         GEMM_SMEM);
    cudaFuncSetAttribute(gemm_hs<1>, cudaFuncAttributeMaxDynamicSharedMemorySize,
                         GEMM_SMEM);
    cudaFuncSetAttribute(flash_attn_s, cudaFuncAttributeMaxDynamicSharedMemorySize,
                         ATTN_SMEM);

    // 0) input prep: x hi/lo split, weights plain fp16 (single launch)
    split_all<<<(N4_ALL + 255) / 256, 256>>>(x, w_qkv, w_out);

    // 1) QKV projection (2-pass) + fused RoPE/split/transpose
    gemm_hs<1><<<dim3(QKV_OUT / 128, S_LEN / 128), 256, GEMM_SMEM>>>(
        xh, xl, wqh, nullptr, cosb, sinb, QKV_OUT, HID);
    // 2) flash attention: S 2-pass (K plain), PV 3-pass
    flash_attn_s<<<dim3(32, NH), 128, ATTN_SMEM>>>();
    // 3) out-projection (2-pass), fp32 out
    gemm_hs<0><<<dim3(HID / 128, S_LEN / 128), 256, GEMM_SMEM>>>(
        ahh, ahl, woh, out, nullptr, nullptr, HID, NH * HD);
}